// round 6
// baseline (speedup 1.0000x reference)
#include <cuda_runtime.h>

// ----------------------------------------------------------------------------
// Problem constants
// ----------------------------------------------------------------------------
#define BATCH 256
#define SEQ 64
#define NG (BATCH*SEQ)          // 16384 graphs
#define NNODES 17
#define NEDGES 81               // 64 edges + 17 self loops
#define CIN0 3
#define HDIM 128                // HEADS*HID = 2*64
#define GROW (NNODES*HDIM)      // 2176 floats per graph
#define MROWS (NG*NNODES)       // 278528 node rows
#define LSTM_IN 2176
#define GATES 512               // 4*128
#define GPC 4                   // graphs per CTA in gat_attn (1 warp/graph)

// ----------------------------------------------------------------------------
// Scratch (device globals). 16B-aligned for float4 access.
// ----------------------------------------------------------------------------
__device__ __align__(16) float g_bufA[NG * GROW];    // 142.6 MB
__device__ __align__(16) float g_bufB[NG * GROW];    // 142.6 MB
__device__ __align__(16) float g_tmpH[NG * GROW];    // 142.6 MB (pre-attention H)
__device__ __align__(16) float g_pre [NG * GATES];   // 33.5 MB
__device__ __align__(16) float g_h1  [NG * HDIM];    // 8.4 MB
__device__ __align__(16) float g_h2  [NG * HDIM];    // 8.4 MB
__device__ __align__(16) float g_hstate[BATCH * HDIM];
__device__ volatile unsigned g_bar_gen;
__device__ unsigned g_bar_cnt;

__device__ __forceinline__ const float* bufsel_r(int s)
{
    switch (s) {
        case 0: return g_bufA;
        case 1: return g_bufB;
        case 2: return g_tmpH;
        case 3: return g_h1;
        default: return g_pre;
    }
}
__device__ __forceinline__ float* bufsel_w(int s)
{
    switch (s) {
        case 0: return g_bufA;
        case 1: return g_bufB;
        case 2: return g_tmpH;
        default: return g_pre;
    }
}

// ----------------------------------------------------------------------------
// Grid barrier for the persistent LSTM kernel (128 CTAs < 148 SMs)
// ----------------------------------------------------------------------------
__device__ __forceinline__ void grid_barrier(unsigned nblocks)
{
    __syncthreads();
    if (threadIdx.x == 0) {
        __threadfence();
        unsigned gen = g_bar_gen;
        if (atomicAdd(&g_bar_cnt, 1u) == nblocks - 1u) {
            g_bar_cnt = 0u;
            __threadfence();
            g_bar_gen = gen + 1u;
        } else {
            while (g_bar_gen == gen) { __nanosleep(64); }
        }
    }
    __syncthreads();
}

// ----------------------------------------------------------------------------
// Layer-0 projection: H0[row,128] = x[row,0:3] @ W0[3,128]
// ----------------------------------------------------------------------------
__global__ void gat_mm0(const float* __restrict__ x, const float* __restrict__ W)
{
    __shared__ float sW[3 * 128];
    const int tid = threadIdx.x;
    for (int i = tid; i < 3 * 128; i += 256) sW[i] = W[i];
    __syncthreads();

    const long i = (long)blockIdx.x * 256 + tid;
    const long row = i >> 5;
    const int q = ((int)(i & 31)) << 2;
    const float x0 = x[row * 3 + 0];
    const float x1 = x[row * 3 + 1];
    const float x2 = x[row * 3 + 2];
    const float4 w0 = *(const float4*)&sW[0 * 128 + q];
    const float4 w1 = *(const float4*)&sW[1 * 128 + q];
    const float4 w2 = *(const float4*)&sW[2 * 128 + q];
    float4 o;
    o.x = x0 * w0.x + x1 * w1.x + x2 * w2.x;
    o.y = x0 * w0.y + x1 * w1.y + x2 * w2.y;
    o.z = x0 * w0.z + x1 * w1.z + x2 * w2.z;
    o.w = x0 * w0.w + x1 * w1.w + x2 * w2.w;
    *(float4*)&g_tmpH[row * 128 + q] = o;
}

// ----------------------------------------------------------------------------
// 128x128 block SGEMM, 256 threads, 8x8 per thread, BK=16, double-buffered.
// TRANSB=false: C = A[M,K] @ B[K,Nn]          TRANSB=true: C = A @ B^T + biases
// ----------------------------------------------------------------------------
template<bool TRANSB>
__global__ void __launch_bounds__(256, 2)
sgemm128(int a_sel, const float* __restrict__ Bmat,
         const float* __restrict__ bias1, const float* __restrict__ bias2,
         int out_sel, int M, int Nn, int K)
{
    const float* A = bufsel_r(a_sel);
    float* C = bufsel_w(out_sel);

    __shared__ __align__(16) float As[2][16][132];
    __shared__ __align__(16) float Bs[2][16][132];

    const int tid = threadIdx.x;
    const int tx = tid & 15;
    const int ty = tid >> 4;
    const int bm = blockIdx.x * 128;
    const int bn = blockIdx.y * 128;

    const int lr = tid >> 1;
    const int lk = (tid & 1) << 3;
    const float* Aptr = A + (long)(bm + lr) * K + lk;
    const int wr = tid >> 4;
    const int wc = (tid & 15) << 3;
    const float* Bptr;
    if (TRANSB) Bptr = Bmat + (long)(bn + lr) * K + lk;
    else        Bptr = Bmat + (long)wr * Nn + bn + wc;

    float acc[8][8];
    #pragma unroll
    for (int i = 0; i < 8; i++)
        #pragma unroll
        for (int j = 0; j < 8; j++) acc[i][j] = 0.f;

    const int NT = K >> 4;
    float pa[8], pb[8];

    {
        const float4 a0 = *(const float4*)(Aptr);
        const float4 a1 = *(const float4*)(Aptr + 4);
        pa[0]=a0.x; pa[1]=a0.y; pa[2]=a0.z; pa[3]=a0.w;
        pa[4]=a1.x; pa[5]=a1.y; pa[6]=a1.z; pa[7]=a1.w;
        const float4 b0 = *(const float4*)(Bptr);
        const float4 b1 = *(const float4*)(Bptr + 4);
        pb[0]=b0.x; pb[1]=b0.y; pb[2]=b0.z; pb[3]=b0.w;
        pb[4]=b1.x; pb[5]=b1.y; pb[6]=b1.z; pb[7]=b1.w;
    }
    #pragma unroll
    for (int i = 0; i < 8; i++) As[0][lk + i][lr] = pa[i];
    if (TRANSB) {
        #pragma unroll
        for (int i = 0; i < 8; i++) Bs[0][lk + i][lr] = pb[i];
    } else {
        *(float4*)&Bs[0][wr][wc]     = make_float4(pb[0], pb[1], pb[2], pb[3]);
        *(float4*)&Bs[0][wr][wc + 4] = make_float4(pb[4], pb[5], pb[6], pb[7]);
    }
    __syncthreads();

    int cur = 0;
    for (int kt = 0; kt < NT; kt++) {
        if (kt + 1 < NT) {
            const long ko = (long)(kt + 1) * 16;
            const float4 a0 = *(const float4*)(Aptr + ko);
            const float4 a1 = *(const float4*)(Aptr + ko + 4);
            pa[0]=a0.x; pa[1]=a0.y; pa[2]=a0.z; pa[3]=a0.w;
            pa[4]=a1.x; pa[5]=a1.y; pa[6]=a1.z; pa[7]=a1.w;
            const float4 b0 = TRANSB ? *(const float4*)(Bptr + ko)
                                     : *(const float4*)(Bptr + ko * Nn);
            const float4 b1 = TRANSB ? *(const float4*)(Bptr + ko + 4)
                                     : *(const float4*)(Bptr + ko * Nn + 4);
            pb[0]=b0.x; pb[1]=b0.y; pb[2]=b0.z; pb[3]=b0.w;
            pb[4]=b1.x; pb[5]=b1.y; pb[6]=b1.z; pb[7]=b1.w;
        }

        #pragma unroll
        for (int kk = 0; kk < 16; kk++) {
            float a[8], b[8];
            const float4 av0 = *(const float4*)&As[cur][kk][ty << 3];
            const float4 av1 = *(const float4*)&As[cur][kk][(ty << 3) + 4];
            a[0]=av0.x; a[1]=av0.y; a[2]=av0.z; a[3]=av0.w;
            a[4]=av1.x; a[5]=av1.y; a[6]=av1.z; a[7]=av1.w;
            const float4 bv0 = *(const float4*)&Bs[cur][kk][tx << 3];
            const float4 bv1 = *(const float4*)&Bs[cur][kk][(tx << 3) + 4];
            b[0]=bv0.x; b[1]=bv0.y; b[2]=bv0.z; b[3]=bv0.w;
            b[4]=bv1.x; b[5]=bv1.y; b[6]=bv1.z; b[7]=bv1.w;
            #pragma unroll
            for (int i = 0; i < 8; i++)
                #pragma unroll
                for (int j = 0; j < 8; j++)
                    acc[i][j] += a[i] * b[j];
        }

        if (kt + 1 < NT) {
            const int nxt = cur ^ 1;
            #pragma unroll
            for (int i = 0; i < 8; i++) As[nxt][lk + i][lr] = pa[i];
            if (TRANSB) {
                #pragma unroll
                for (int i = 0; i < 8; i++) Bs[nxt][lk + i][lr] = pb[i];
            } else {
                *(float4*)&Bs[nxt][wr][wc]     = make_float4(pb[0], pb[1], pb[2], pb[3]);
                *(float4*)&Bs[nxt][wr][wc + 4] = make_float4(pb[4], pb[5], pb[6], pb[7]);
            }
            __syncthreads();
            cur = nxt;
        }
    }

    #pragma unroll
    for (int i = 0; i < 8; i++) {
        const long row = bm + (ty << 3) + i;
        #pragma unroll
        for (int j = 0; j < 8; j += 4) {
            const int col = bn + (tx << 3) + j;
            float4 v = make_float4(acc[i][j], acc[i][j+1], acc[i][j+2], acc[i][j+3]);
            if (TRANSB) {
                v.x += bias1[col]     + bias2[col];
                v.y += bias1[col + 1] + bias2[col + 1];
                v.z += bias1[col + 2] + bias2[col + 2];
                v.w += bias1[col + 3] + bias2[col + 3];
            }
            *(float4*)&C[row * Nn + col] = v;
        }
    }
}

// ----------------------------------------------------------------------------
// GAT attention v3: 4 graphs/CTA, 128 threads, ONE WARP PER GRAPH, with each
// warp staging its own graph's H (8.5 KB) in smem via a coalesced copy.
// All gather phases hit smem; no cross-warp sync after the init barrier.
// ----------------------------------------------------------------------------
__global__ void __launch_bounds__(128)
gat_attn(const float* __restrict__ a_src, const float* __restrict__ a_dst,
         const float* __restrict__ bias, const int* __restrict__ edge_index,
         int out_sel, int relu_flag)
{
    __shared__ __align__(16) float sH[GPC][GROW];     // 34816 B
    __shared__ float sAs[128], sAd[128], sB[128];
    __shared__ int s_src[NEDGES], s_dst[NEDGES], s_cs[NNODES + 1], s_ce[NEDGES];
    __shared__ float s_as[GPC][36];
    __shared__ float s_ad[GPC][36];
    __shared__ float s_m [GPC][36];
    __shared__ float s_dn[GPC][36];
    __shared__ float s_ev[GPC][164];

    const int tid = threadIdx.x;
    const int wid = tid >> 5, lane = tid & 31;

    if (tid < 128) { sAs[tid] = a_src[tid]; sAd[tid] = a_dst[tid]; sB[tid] = bias[tid]; }
    if (tid == 0) {
        int cnt[NNODES];
        for (int n = 0; n < NNODES; n++) cnt[n] = 0;
        for (int e = 0; e < NEDGES; e++) {
            int s = (e < 64) ? edge_index[e]      : (e - 64);
            int d = (e < 64) ? edge_index[64 + e] : (e - 64);
            s_src[e] = s; s_dst[e] = d; cnt[d]++;
        }
        int off = 0;
        for (int n = 0; n < NNODES; n++) { s_cs[n] = off; off += cnt[n]; cnt[n] = s_cs[n]; }
        s_cs[NNODES] = off;
        for (int e = 0; e < NEDGES; e++) s_ce[cnt[s_dst[e]]++] = e;
    }
    __syncthreads();

    const long g = (long)blockIdx.x * GPC + wid;
    float* Hw = sH[wid];

    // each warp copies its own graph's H: 2176 floats = 544 float4, coalesced
    {
        const float4* src4 = (const float4*)(g_tmpH + g * GROW);
        float4* dst4 = (float4*)Hw;
        #pragma unroll
        for (int i = 0; i < 17; i++)
            dst4[i * 32 + lane] = src4[i * 32 + lane];
    }
    __syncwarp();

    const int hh = lane >> 4;
    const int q  = lane << 2;

    // phase 1: per-node logits via half-warp reductions
    #pragma unroll
    for (int n = 0; n < NNODES; n++) {
        const float4 hv = *(const float4*)&Hw[n * 128 + q];
        float pas = hv.x * sAs[q] + hv.y * sAs[q + 1] + hv.z * sAs[q + 2] + hv.w * sAs[q + 3];
        float pad_ = hv.x * sAd[q] + hv.y * sAd[q + 1] + hv.z * sAd[q + 2] + hv.w * sAd[q + 3];
        #pragma unroll
        for (int off = 8; off > 0; off >>= 1) {
            pas  += __shfl_xor_sync(0xffffffffu, pas, off);
            pad_ += __shfl_xor_sync(0xffffffffu, pad_, off);
        }
        if ((lane & 15) == 0) {
            s_as[wid][n * 2 + hh] = pas;
            s_ad[wid][n * 2 + hh] = pad_;
        }
    }
    __syncwarp();

    // phase 2: edge logits (leaky relu)
    for (int t = lane; t < 2 * NEDGES; t += 32) {
        const int e = t >> 1, h2 = t & 1;
        const float raw = s_as[wid][s_src[e] * 2 + h2] + s_ad[wid][s_dst[e] * 2 + h2];
        s_ev[wid][t] = raw > 0.f ? raw : 0.2f * raw;
    }
    __syncwarp();

    // per-dst max + denominator: 34 tasks on 32 lanes (strided)
    for (int t = lane; t < 2 * NNODES; t += 32) {
        const int n = t >> 1, h2 = t & 1;
        float m = -1e30f;
        for (int p = s_cs[n]; p < s_cs[n + 1]; p++)
            m = fmaxf(m, s_ev[wid][s_ce[p] * 2 + h2]);
        float den = 0.f;
        for (int p = s_cs[n]; p < s_cs[n + 1]; p++)
            den += __expf(s_ev[wid][s_ce[p] * 2 + h2] - m);
        s_m[wid][t] = m; s_dn[wid][t] = den;
    }
    __syncwarp();

    // alpha
    for (int t = lane; t < 2 * NEDGES; t += 32) {
        const int e = t >> 1, h2 = t & 1;
        const int d = s_dst[e];
        s_ev[wid][t] = __expf(s_ev[wid][t] - s_m[wid][d * 2 + h2])
                       / (s_dn[wid][d * 2 + h2] + 1e-16f);
    }
    __syncwarp();

    // phase 3: aggregation + bias (+relu), gathers from smem
    float* outg = bufsel_w(out_sel) + g * GROW;
    const float4 b4 = *(const float4*)&sB[q];
    #pragma unroll
    for (int n = 0; n < NNODES; n++) {
        float4 acc = b4;
        for (int p = s_cs[n]; p < s_cs[n + 1]; p++) {
            const int e = s_ce[p];
            const float al = s_ev[wid][e * 2 + hh];
            const float4 hv = *(const float4*)&Hw[s_src[e] * 128 + q];
            acc.x += al * hv.x; acc.y += al * hv.y;
            acc.z += al * hv.z; acc.w += al * hv.w;
        }
        if (relu_flag) {
            acc.x = fmaxf(acc.x, 0.f); acc.y = fmaxf(acc.y, 0.f);
            acc.z = fmaxf(acc.z, 0.f); acc.w = fmaxf(acc.w, 0.f);
        }
        *(float4*)&outg[n * 128 + q] = acc;
    }
}

// ----------------------------------------------------------------------------
// LSTM recurrence (persistent, 128 CTAs) — reverted to the proven R3 version.
// row = tid>>5, l = tid&31; whh slice in smem, stride 129.
// ----------------------------------------------------------------------------
__global__ void lstm_recur(const float* __restrict__ whh, int out_sel)
{
    extern __shared__ __align__(16) float smem[];
    float* sW = smem;              // 128*129
    float* sH = sW + 128 * 129;    // 8*128
    float* sC = sH + 8 * 128;      // 8*32

    float* hseq = (out_sel == 0) ? g_h1 : g_h2;
    const float* pre = g_pre;

    const int tid = threadIdx.x;
    const int b0 = blockIdx.x * 8;
    const int d0 = blockIdx.y * 32;
    const unsigned nblocks = gridDim.x * gridDim.y;

    for (int i = tid; i < 128 * 128; i += blockDim.x) {
        const int r = i >> 7, k = i & 127;
        const int j = ((r >> 5) << 7) + d0 + (r & 31);
        sW[r * 129 + k] = whh[j * 128 + k];
    }
    {
        const int row = tid >> 5, l = tid & 31;
        sC[row * 32 + l] = 0.f;
        g_hstate[(b0 + row) * 128 + d0 + l] = 0.f;
    }
    grid_barrier(nblocks);

    for (int t = 0; t < SEQ; t++) {
        for (int i = tid; i < 8 * 128; i += blockDim.x) {
            const int row = i >> 7, k = i & 127;
            sH[i] = __ldcg(&g_hstate[(b0 + row) * 128 + k]);
        }
        __syncthreads();

        {
            const int row = tid >> 5, l = tid & 31;
            const float* hp = &sH[row * 128];
            const float* w0 = &sW[(l)      * 129];
            const float* w1 = &sW[(32 + l) * 129];
            const float* w2 = &sW[(64 + l) * 129];
            const float* w3 = &sW[(96 + l) * 129];
            const long pbase = ((long)(b0 + row) * SEQ + t) * GATES;
            float a0 = pre[pbase +       d0 + l];
            float a1 = pre[pbase + 128 + d0 + l];
            float a2 = pre[pbase + 256 + d0 + l];
            float a3 = pre[pbase + 384 + d0 + l];
            #pragma unroll 4
            for (int k = 0; k < 128; k++) {
                const float hv = hp[k];
                a0 += hv * w0[k]; a1 += hv * w1[k];
                a2 += hv * w2[k]; a3 += hv * w3[k];
            }
            const float ig = 1.f / (1.f + expf(-a0));
            const float fg = 1.f / (1.f + expf(-a1));
            const float gg = tanhf(a2);
            const float og = 1.f / (1.f + expf(-a3));
            const float c = fg * sC[row * 32 + l] + ig * gg;
            sC[row * 32 + l] = c;
            const float h = og * tanhf(c);
            g_hstate[(b0 + row) * 128 + d0 + l] = h;
            hseq[((long)(b0 + row) * SEQ + t) * 128 + d0 + l] = h;
        }
        grid_barrier(nblocks);
    }
}

// ----------------------------------------------------------------------------
// Temporal attention + FC head. One CTA (128 threads) per batch row.
// ----------------------------------------------------------------------------
__global__ void attn_fc(const float* __restrict__ attn_w, const float* __restrict__ attn_b,
                        const float* __restrict__ fc_w,   const float* __restrict__ fc_b,
                        float* __restrict__ out)
{
    __shared__ float sw[128];
    __shared__ float sc[SEQ];
    __shared__ float sctx[128];

    const int b = blockIdx.x, tid = threadIdx.x;
    const float* h2 = g_h2 + (long)b * SEQ * 128;

    sw[tid] = attn_w[tid];
    __syncthreads();

    if (tid < SEQ) {
        const float* hp = h2 + tid * 128;
        float acc = attn_b[0];
        #pragma unroll 8
        for (int k = 0; k < 128; k++) acc += hp[k] * sw[k];
        sc[tid] = tanhf(acc);
    }
    __syncthreads();

    if (tid == 0) {
        float m = -1e30f;
        for (int t = 0; t < SEQ; t++) m = fmaxf(m, sc[t]);
        float s = 0.f;
        for (int t = 0; t < SEQ; t++) { sc[t] = __expf(sc[t] - m); s += sc[t]; }
        const float inv = 1.f / s;
        for (int t = 0; t < SEQ; t++) sc[t] *= inv;
    }
    __syncthreads();

    {
        float acc = 0.f;
        for (int t = 0; t < SEQ; t++) acc += sc[t] * h2[t * 128 + tid];
        sctx[tid] = acc;
    }
    __syncthreads();

    if (tid < 10) {
        float acc = fc_b[tid];
        #pragma unroll 8
        for (int k = 0; k < 128; k++) acc += sctx[k] * fc_w[tid * 128 + k];
        out[b * 10 + tid] = acc;
    }
}

// ----------------------------------------------------------------------------
// Launcher
// ----------------------------------------------------------------------------
extern "C" void kernel_launch(void* const* d_in, const int* in_sizes, int n_in,
                              void* d_out, int out_size)
{
    const float* x    = (const float*)d_in[0];
    const int*   eidx = (const int*)  d_in[1];
    const float* gw[4]  = { (const float*)d_in[2],  (const float*)d_in[6],
                            (const float*)d_in[10], (const float*)d_in[14] };
    const float* gas[4] = { (const float*)d_in[3],  (const float*)d_in[7],
                            (const float*)d_in[11], (const float*)d_in[15] };
    const float* gad[4] = { (const float*)d_in[4],  (const float*)d_in[8],
                            (const float*)d_in[12], (const float*)d_in[16] };
    const float* gb[4]  = { (const float*)d_in[5],  (const float*)d_in[9],
                            (const float*)d_in[13], (const float*)d_in[17] };
    const float* wih0 = (const float*)d_in[18];
    const float* whh0 = (const float*)d_in[19];
    const float* bih0 = (const float*)d_in[20];
    const float* bhh0 = (const float*)d_in[21];
    const float* wih1 = (const float*)d_in[22];
    const float* whh1 = (const float*)d_in[23];
    const float* bih1 = (const float*)d_in[24];
    const float* bhh1 = (const float*)d_in[25];
    const float* attn_w = (const float*)d_in[26];
    const float* attn_b = (const float*)d_in[27];
    const float* fc_w   = (const float*)d_in[28];
    const float* fc_b   = (const float*)d_in[29];
    float* out = (float*)d_out;

    const int smem_rec = (128 * 129 + 8 * 128 + 8 * 32) * 4;
    cudaFuncSetAttribute((const void*)lstm_recur,
                         cudaFuncAttributeMaxDynamicSharedMemorySize, smem_rec);

    const int attn_grid = NG / GPC;      // 4096
    const int mm_grid   = MROWS / 128;   // 2176

    // ---- GAT layer 0: x @ W0 -> tmpH -> attn -> bufA (relu)
    gat_mm0<<<(MROWS * 32) / 256, 256>>>(x, gw[0]);
    gat_attn<<<attn_grid, 128>>>(gas[0], gad[0], gb[0], eidx, 0, 1);

    // ---- GAT layer 1: bufA @ W1 -> tmpH -> attn -> bufB
    sgemm128<false><<<dim3(mm_grid, 1), 256>>>(0, gw[1], nullptr, nullptr, 2, MROWS, 128, 128);
    gat_attn<<<attn_grid, 128>>>(gas[1], gad[1], gb[1], eidx, 1, 0);

    // ---- GAT layer 2: bufB @ W2 -> tmpH -> attn -> bufA (relu)
    sgemm128<false><<<dim3(mm_grid, 1), 256>>>(1, gw[2], nullptr, nullptr, 2, MROWS, 128, 128);
    gat_attn<<<attn_grid, 128>>>(gas[2], gad[2], gb[2], eidx, 0, 1);

    // ---- GAT layer 3: bufA @ W3 -> tmpH -> attn -> bufB
    sgemm128<false><<<dim3(mm_grid, 1), 256>>>(0, gw[3], nullptr, nullptr, 2, MROWS, 128, 128);
    gat_attn<<<attn_grid, 128>>>(gas[3], gad[3], gb[3], eidx, 1, 0);

    // ---- LSTM layer 0: pre-gates GEMM (A = bufB viewed [16384, 2176]) + recurrence
    sgemm128<true><<<dim3(NG / 128, GATES / 128), 256>>>(1, wih0, bih0, bhh0, 4, NG, GATES, LSTM_IN);
    lstm_recur<<<dim3(32, 4), 256, smem_rec>>>(whh0, 0);

    // ---- LSTM layer 1: pre-gates GEMM (A = g_h1 [16384,128]) + recurrence
    sgemm128<true><<<dim3(NG / 128, GATES / 128), 256>>>(3, wih1, bih1, bhh1, 4, NG, GATES, HDIM);
    lstm_recur<<<dim3(32, 4), 256, smem_rec>>>(whh1, 1);

    // ---- head
    attn_fc<<<BATCH, 128>>>(attn_w, attn_b, fc_w, fc_b, out);
}

// round 7
// speedup vs baseline: 1.7351x; 1.7351x over previous
#include <cuda_runtime.h>

// ----------------------------------------------------------------------------
// Problem constants
// ----------------------------------------------------------------------------
#define BATCH 256
#define SEQ 64
#define NG (BATCH*SEQ)          // 16384 graphs
#define NNODES 17
#define NEDGES 81               // 64 edges + 17 self loops
#define HDIM 128                // HEADS*HID = 2*64
#define GROW (NNODES*HDIM)      // 2176 floats per graph
#define MROWS (NG*NNODES)       // 278528 node rows
#define LSTM_IN 2176
#define GATES 512               // 4*128

// ----------------------------------------------------------------------------
// Scratch (device globals). 16B-aligned for float4 access.
// ----------------------------------------------------------------------------
__device__ __align__(16) float g_bufA[NG * GROW];    // 142.6 MB
__device__ __align__(16) float g_bufB[NG * GROW];    // 142.6 MB
__device__ __align__(16) float g_tmpH[NG * GROW];    // 142.6 MB (pre-attention H)
__device__ __align__(16) float g_pre [NG * GATES];   // 33.5 MB
__device__ __align__(16) float g_h1  [NG * HDIM];    // 8.4 MB
__device__ __align__(16) float g_h2  [NG * HDIM];    // 8.4 MB
__device__ __align__(16) float g_hstate[BATCH * HDIM];
__device__ volatile unsigned g_bar_gen;
__device__ unsigned g_bar_cnt;

__device__ __forceinline__ const float* bufsel_r(int s)
{
    switch (s) {
        case 0: return g_bufA;
        case 1: return g_bufB;
        case 2: return g_tmpH;
        case 3: return g_h1;
        default: return g_pre;
    }
}
__device__ __forceinline__ float* bufsel_w(int s)
{
    switch (s) {
        case 0: return g_bufA;
        case 1: return g_bufB;
        case 2: return g_tmpH;
        default: return g_pre;
    }
}

// ----------------------------------------------------------------------------
// Grid barrier for the persistent LSTM kernel (128 CTAs < 148 SMs)
// ----------------------------------------------------------------------------
__device__ __forceinline__ void grid_barrier(unsigned nblocks)
{
    __syncthreads();
    if (threadIdx.x == 0) {
        __threadfence();
        unsigned gen = g_bar_gen;
        if (atomicAdd(&g_bar_cnt, 1u) == nblocks - 1u) {
            g_bar_cnt = 0u;
            __threadfence();
            g_bar_gen = gen + 1u;
        } else {
            while (g_bar_gen == gen) { __nanosleep(64); }
        }
    }
    __syncthreads();
}

// ----------------------------------------------------------------------------
// Layer-0 projection: H0[row,128] = x[row,0:3] @ W0[3,128]
// ----------------------------------------------------------------------------
__global__ void gat_mm0(const float* __restrict__ x, const float* __restrict__ W)
{
    __shared__ float sW[3 * 128];
    const int tid = threadIdx.x;
    for (int i = tid; i < 3 * 128; i += 256) sW[i] = W[i];
    __syncthreads();

    const long i = (long)blockIdx.x * 256 + tid;
    const long row = i >> 5;
    const int q = ((int)(i & 31)) << 2;
    const float x0 = x[row * 3 + 0];
    const float x1 = x[row * 3 + 1];
    const float x2 = x[row * 3 + 2];
    const float4 w0 = *(const float4*)&sW[0 * 128 + q];
    const float4 w1 = *(const float4*)&sW[1 * 128 + q];
    const float4 w2 = *(const float4*)&sW[2 * 128 + q];
    float4 o;
    o.x = x0 * w0.x + x1 * w1.x + x2 * w2.x;
    o.y = x0 * w0.y + x1 * w1.y + x2 * w2.y;
    o.z = x0 * w0.z + x1 * w1.z + x2 * w2.z;
    o.w = x0 * w0.w + x1 * w1.w + x2 * w2.w;
    *(float4*)&g_tmpH[row * 128 + q] = o;
}

// ----------------------------------------------------------------------------
// 128x128 block SGEMM, 256 threads, 8x8 per thread, BK=16, double-buffered.
// Inner product uses packed fma.rn.f32x2 (FFMA2): 2x fp32 FMA throughput,
// bit-exact IEEE fp32 per lane.
// TRANSB=false: C = A[M,K] @ B[K,Nn]          TRANSB=true: C = A @ B^T + biases
// ----------------------------------------------------------------------------
template<bool TRANSB>
__global__ void __launch_bounds__(256, 2)
sgemm128(int a_sel, const float* __restrict__ Bmat,
         const float* __restrict__ bias1, const float* __restrict__ bias2,
         int out_sel, int M, int Nn, int K)
{
    const float* A = bufsel_r(a_sel);
    float* C = bufsel_w(out_sel);

    __shared__ __align__(16) float As[2][16][132];
    __shared__ __align__(16) float Bs[2][16][132];

    const int tid = threadIdx.x;
    const int tx = tid & 15;
    const int ty = tid >> 4;
    const int bm = blockIdx.x * 128;
    const int bn = blockIdx.y * 128;

    const int lr = tid >> 1;
    const int lk = (tid & 1) << 3;
    const float* Aptr = A + (long)(bm + lr) * K + lk;
    const int wr = tid >> 4;
    const int wc = (tid & 15) << 3;
    const float* Bptr;
    if (TRANSB) Bptr = Bmat + (long)(bn + lr) * K + lk;
    else        Bptr = Bmat + (long)wr * Nn + bn + wc;

    // packed accumulators: acc2[i][p] = (C[i][2p], C[i][2p+1])
    unsigned long long acc2[8][4];
    #pragma unroll
    for (int i = 0; i < 8; i++)
        #pragma unroll
        for (int p = 0; p < 4; p++) acc2[i][p] = 0ull;

    const int NT = K >> 4;
    float pa[8], pb[8];

    {
        const float4 a0 = *(const float4*)(Aptr);
        const float4 a1 = *(const float4*)(Aptr + 4);
        pa[0]=a0.x; pa[1]=a0.y; pa[2]=a0.z; pa[3]=a0.w;
        pa[4]=a1.x; pa[5]=a1.y; pa[6]=a1.z; pa[7]=a1.w;
        const float4 b0 = *(const float4*)(Bptr);
        const float4 b1 = *(const float4*)(Bptr + 4);
        pb[0]=b0.x; pb[1]=b0.y; pb[2]=b0.z; pb[3]=b0.w;
        pb[4]=b1.x; pb[5]=b1.y; pb[6]=b1.z; pb[7]=b1.w;
    }
    #pragma unroll
    for (int i = 0; i < 8; i++) As[0][lk + i][lr] = pa[i];
    if (TRANSB) {
        #pragma unroll
        for (int i = 0; i < 8; i++) Bs[0][lk + i][lr] = pb[i];
    } else {
        *(float4*)&Bs[0][wr][wc]     = make_float4(pb[0], pb[1], pb[2], pb[3]);
        *(float4*)&Bs[0][wr][wc + 4] = make_float4(pb[4], pb[5], pb[6], pb[7]);
    }
    __syncthreads();

    int cur = 0;
    for (int kt = 0; kt < NT; kt++) {
        if (kt + 1 < NT) {
            const long ko = (long)(kt + 1) * 16;
            const float4 a0 = *(const float4*)(Aptr + ko);
            const float4 a1 = *(const float4*)(Aptr + ko + 4);
            pa[0]=a0.x; pa[1]=a0.y; pa[2]=a0.z; pa[3]=a0.w;
            pa[4]=a1.x; pa[5]=a1.y; pa[6]=a1.z; pa[7]=a1.w;
            const float4 b0 = TRANSB ? *(const float4*)(Bptr + ko)
                                     : *(const float4*)(Bptr + ko * Nn);
            const float4 b1 = TRANSB ? *(const float4*)(Bptr + ko + 4)
                                     : *(const float4*)(Bptr + ko * Nn + 4);
            pb[0]=b0.x; pb[1]=b0.y; pb[2]=b0.z; pb[3]=b0.w;
            pb[4]=b1.x; pb[5]=b1.y; pb[6]=b1.z; pb[7]=b1.w;
        }

        #pragma unroll
        for (int kk = 0; kk < 16; kk++) {
            const float4 av0 = *(const float4*)&As[cur][kk][ty << 3];
            const float4 av1 = *(const float4*)&As[cur][kk][(ty << 3) + 4];
            const float4 bv0 = *(const float4*)&Bs[cur][kk][tx << 3];
            const float4 bv1 = *(const float4*)&Bs[cur][kk][(tx << 3) + 4];

            unsigned long long b2[4];
            asm("mov.b64 %0, {%1, %2};" : "=l"(b2[0]) : "f"(bv0.x), "f"(bv0.y));
            asm("mov.b64 %0, {%1, %2};" : "=l"(b2[1]) : "f"(bv0.z), "f"(bv0.w));
            asm("mov.b64 %0, {%1, %2};" : "=l"(b2[2]) : "f"(bv1.x), "f"(bv1.y));
            asm("mov.b64 %0, {%1, %2};" : "=l"(b2[3]) : "f"(bv1.z), "f"(bv1.w));

            const float af[8] = { av0.x, av0.y, av0.z, av0.w,
                                  av1.x, av1.y, av1.z, av1.w };
            unsigned long long a2[8];
            #pragma unroll
            for (int i = 0; i < 8; i++)
                asm("mov.b64 %0, {%1, %1};" : "=l"(a2[i]) : "f"(af[i]));

            #pragma unroll
            for (int i = 0; i < 8; i++)
                #pragma unroll
                for (int p = 0; p < 4; p++)
                    asm("fma.rn.f32x2 %0, %1, %2, %0;"
                        : "+l"(acc2[i][p]) : "l"(a2[i]), "l"(b2[p]));
        }

        if (kt + 1 < NT) {
            const int nxt = cur ^ 1;
            #pragma unroll
            for (int i = 0; i < 8; i++) As[nxt][lk + i][lr] = pa[i];
            if (TRANSB) {
                #pragma unroll
                for (int i = 0; i < 8; i++) Bs[nxt][lk + i][lr] = pb[i];
            } else {
                *(float4*)&Bs[nxt][wr][wc]     = make_float4(pb[0], pb[1], pb[2], pb[3]);
                *(float4*)&Bs[nxt][wr][wc + 4] = make_float4(pb[4], pb[5], pb[6], pb[7]);
            }
            __syncthreads();
            cur = nxt;
        }
    }

    // epilogue: unpack f32x2 accumulators, add biases (TRANSB), store float4
    #pragma unroll
    for (int i = 0; i < 8; i++) {
        const long row = bm + (ty << 3) + i;
        float o[8];
        #pragma unroll
        for (int p = 0; p < 4; p++)
            asm("mov.b64 {%0, %1}, %2;" : "=f"(o[2*p]), "=f"(o[2*p+1]) : "l"(acc2[i][p]));
        #pragma unroll
        for (int j = 0; j < 8; j += 4) {
            const int col = bn + (tx << 3) + j;
            float4 v = make_float4(o[j], o[j+1], o[j+2], o[j+3]);
            if (TRANSB) {
                v.x += bias1[col]     + bias2[col];
                v.y += bias1[col + 1] + bias2[col + 1];
                v.z += bias1[col + 2] + bias2[col + 2];
                v.w += bias1[col + 3] + bias2[col + 3];
            }
            *(float4*)&C[row * Nn + col] = v;
        }
    }
}

// ----------------------------------------------------------------------------
// GAT attention + aggregation (EXACT R3 version, measured 226.6us/layer).
// 8 graphs per CTA, 256 threads, all phases block-parallel, H staged in smem.
// ----------------------------------------------------------------------------
__global__ void gat_attn(const float* __restrict__ a_src, const float* __restrict__ a_dst,
                         const float* __restrict__ bias, const int* __restrict__ edge_index,
                         int out_sel, int relu_flag)
{
    extern __shared__ __align__(16) float smem[];
    float* sH   = smem;                    // 8*2176 = 17408
    float* sAs  = sH  + 8 * GROW;          // 128
    float* sAd  = sAs + 128;               // 128
    float* sB   = sAd + 128;               // 128
    float* s_as = sB  + 128;               // 8*34 = 272
    float* s_ad = s_as + 272;
    float* s_m  = s_ad + 272;
    float* s_dn = s_m  + 272;
    float* s_ev = s_dn + 272;              // 8*162 = 1296
    int*   s_src = (int*)(s_ev + 1296);    // 81
    int*   s_dst = s_src + NEDGES;         // 81
    int*   s_cs  = s_dst + NEDGES;         // 18
    int*   s_ce  = s_cs + NNODES + 1;      // 81

    const int tid = threadIdx.x;

    if (tid == 0) {
        int cnt[NNODES];
        for (int n = 0; n < NNODES; n++) cnt[n] = 0;
        for (int e = 0; e < NEDGES; e++) {
            int s = (e < 64) ? edge_index[e]      : (e - 64);
            int d = (e < 64) ? edge_index[64 + e] : (e - 64);
            s_src[e] = s; s_dst[e] = d; cnt[d]++;
        }
        int off = 0;
        for (int n = 0; n < NNODES; n++) { s_cs[n] = off; off += cnt[n]; cnt[n] = s_cs[n]; }
        s_cs[NNODES] = off;
        for (int e = 0; e < NEDGES; e++) s_ce[cnt[s_dst[e]]++] = e;
    }
    if (tid < 128) { sAs[tid] = a_src[tid]; sAd[tid] = a_dst[tid]; sB[tid] = bias[tid]; }

    const float* Hsrc = g_tmpH + (long)blockIdx.x * (8 * GROW);
    for (int i = tid; i < (8 * GROW) / 4; i += 256)
        *(float4*)&sH[i * 4] = *(const float4*)&Hsrc[i * 4];
    __syncthreads();

    for (int i = tid; i < 8 * 64; i += 256) {
        const int g = i >> 6, t = i & 63;
        if (t < 34) {
            const int n = t >> 1, hh = t & 1;
            const float* hp = &sH[g * GROW + n * 128 + hh * 64];
            float as = 0.f, ad = 0.f;
            #pragma unroll 8
            for (int d = 0; d < 64; d++) {
                as += hp[d] * sAs[hh * 64 + d];
                ad += hp[d] * sAd[hh * 64 + d];
            }
            s_as[g * 34 + t] = as; s_ad[g * 34 + t] = ad;
        }
    }
    __syncthreads();

    for (int i = tid; i < 8 * 256; i += 256) {
        const int g = i >> 8, t = i & 255;
        if (t < 162) {
            const int e = t >> 1, hh = t & 1;
            const float raw = s_as[g * 34 + s_src[e] * 2 + hh]
                            + s_ad[g * 34 + s_dst[e] * 2 + hh];
            s_ev[g * 162 + t] = raw > 0.f ? raw : 0.2f * raw;
        }
    }
    __syncthreads();

    for (int i = tid; i < 8 * 64; i += 256) {
        const int g = i >> 6, t = i & 63;
        if (t < 34) {
            const int n = t >> 1, hh = t & 1;
            float m = -1e30f;
            for (int p = s_cs[n]; p < s_cs[n + 1]; p++)
                m = fmaxf(m, s_ev[g * 162 + s_ce[p] * 2 + hh]);
            float den = 0.f;
            for (int p = s_cs[n]; p < s_cs[n + 1]; p++)
                den += __expf(s_ev[g * 162 + s_ce[p] * 2 + hh] - m);
            s_m[g * 34 + t] = m; s_dn[g * 34 + t] = den;
        }
    }
    __syncthreads();

    for (int i = tid; i < 8 * 256; i += 256) {
        const int g = i >> 8, t = i & 255;
        if (t < 162) {
            const int e = t >> 1, hh = t & 1;
            const int d = s_dst[e];
            s_ev[g * 162 + t] = __expf(s_ev[g * 162 + t] - s_m[g * 34 + d * 2 + hh])
                                / (s_dn[g * 34 + d * 2 + hh] + 1e-16f);
        }
    }
    __syncthreads();

    float* outb = bufsel_w(out_sel);
    for (int i = tid; i < 8 * NNODES * 32; i += 256) {
        const int g = i / (NNODES * 32);
        const int r = i - g * (NNODES * 32);
        const int n = r >> 5;
        const int q = (r & 31) << 2;
        const int hh = q >> 6;
        float4 acc = make_float4(0.f, 0.f, 0.f, 0.f);
        for (int p = s_cs[n]; p < s_cs[n + 1]; p++) {
            const int e = s_ce[p];
            const float al = s_ev[g * 162 + e * 2 + hh];
            const float4 hv = *(const float4*)&sH[g * GROW + s_src[e] * 128 + q];
            acc.x += al * hv.x; acc.y += al * hv.y;
            acc.z += al * hv.z; acc.w += al * hv.w;
        }
        const float4 b4 = *(const float4*)&sB[q];
        acc.x += b4.x; acc.y += b4.y; acc.z += b4.z; acc.w += b4.w;
        if (relu_flag) {
            acc.x = fmaxf(acc.x, 0.f); acc.y = fmaxf(acc.y, 0.f);
            acc.z = fmaxf(acc.z, 0.f); acc.w = fmaxf(acc.w, 0.f);
        }
        *(float4*)&outb[((long)blockIdx.x * 8 + g) * GROW + n * 128 + q] = acc;
    }
}

// ----------------------------------------------------------------------------
// LSTM recurrence (persistent, 128 CTAs) — proven R3 version.
// ----------------------------------------------------------------------------
__global__ void lstm_recur(const float* __restrict__ whh, int out_sel)
{
    extern __shared__ __align__(16) float smem[];
    float* sW = smem;              // 128*129
    float* sH = sW + 128 * 129;    // 8*128
    float* sC = sH + 8 * 128;      // 8*32

    float* hseq = (out_sel == 0) ? g_h1 : g_h2;
    const float* pre = g_pre;

    const int tid = threadIdx.x;
    const int b0 = blockIdx.x * 8;
    const int d0 = blockIdx.y * 32;
    const unsigned nblocks = gridDim.x * gridDim.y;

    for (int i = tid; i < 128 * 128; i += blockDim.x) {
        const int r = i >> 7, k = i & 127;
        const int j = ((r >> 5) << 7) + d0 + (r & 31);
        sW[r * 129 + k] = whh[j * 128 + k];
    }
    {
        const int row = tid >> 5, l = tid & 31;
        sC[row * 32 + l] = 0.f;
        g_hstate[(b0 + row) * 128 + d0 + l] = 0.f;
    }
    grid_barrier(nblocks);

    for (int t = 0; t < SEQ; t++) {
        for (int i = tid; i < 8 * 128; i += blockDim.x) {
            const int row = i >> 7, k = i & 127;
            sH[i] = __ldcg(&g_hstate[(b0 + row) * 128 + k]);
        }
        __syncthreads();

        {
            const int row = tid >> 5, l = tid & 31;
            const float* hp = &sH[row * 128];
            const float* w0 = &sW[(l)      * 129];
            const float* w1 = &sW[(32 + l) * 129];
            const float* w2 = &sW[(64 + l) * 129];
            const float* w3 = &sW[(96 + l) * 129];
            const long pbase = ((long)(b0 + row) * SEQ + t) * GATES;
            float a0 = pre[pbase +       d0 + l];
            float a1 = pre[pbase + 128 + d0 + l];
            float a2 = pre[pbase + 256 + d0 + l];
            float a3 = pre[pbase + 384 + d0 + l];
            #pragma unroll 4
            for (int k = 0; k < 128; k++) {
                const float hv = hp[k];
                a0 += hv * w0[k]; a1 += hv * w1[k];
                a2 += hv * w2[k]; a3 += hv * w3[k];
            }
            const float ig = 1.f / (1.f + expf(-a0));
            const float fg = 1.f / (1.f + expf(-a1));
            const float gg = tanhf(a2);
            const float og = 1.f / (1.f + expf(-a3));
            const float c = fg * sC[row * 32 + l] + ig * gg;
            sC[row * 32 + l] = c;
            const float h = og * tanhf(c);
            g_hstate[(b0 + row) * 128 + d0 + l] = h;
            hseq[((long)(b0 + row) * SEQ + t) * 128 + d0 + l] = h;
        }
        grid_barrier(nblocks);
    }
}

// ----------------------------------------------------------------------------
// Temporal attention + FC head. One CTA (128 threads) per batch row.
// ----------------------------------------------------------------------------
__global__ void attn_fc(const float* __restrict__ attn_w, const float* __restrict__ attn_b,
                        const float* __restrict__ fc_w,   const float* __restrict__ fc_b,
                        float* __restrict__ out)
{
    __shared__ float sw[128];
    __shared__ float sc[SEQ];
    __shared__ float sctx[128];

    const int b = blockIdx.x, tid = threadIdx.x;
    const float* h2 = g_h2 + (long)b * SEQ * 128;

    sw[tid] = attn_w[tid];
    __syncthreads();

    if (tid < SEQ) {
        const float* hp = h2 + tid * 128;
        float acc = attn_b[0];
        #pragma unroll 8
        for (int k = 0; k < 128; k++) acc += hp[k] * sw[k];
        sc[tid] = tanhf(acc);
    }
    __syncthreads();

    if (tid == 0) {
        float m = -1e30f;
        for (int t = 0; t < SEQ; t++) m = fmaxf(m, sc[t]);
        float s = 0.f;
        for (int t = 0; t < SEQ; t++) { sc[t] = __expf(sc[t] - m); s += sc[t]; }
        const float inv = 1.f / s;
        for (int t = 0; t < SEQ; t++) sc[t] *= inv;
    }
    __syncthreads();

    {
        float acc = 0.f;
        for (int t = 0; t < SEQ; t++) acc += sc[t] * h2[t * 128 + tid];
        sctx[tid] = acc;
    }
    __syncthreads();

    if (tid < 10) {
        float acc = fc_b[tid];
        #pragma unroll 8
        for (int k = 0; k < 128; k++) acc += sctx[k] * fc_w[tid * 128 + k];
        out[b * 10 + tid] = acc;
    }
}

// ----------------------------------------------------------------------------
// Launcher
// ----------------------------------------------------------------------------
extern "C" void kernel_launch(void* const* d_in, const int* in_sizes, int n_in,
                              void* d_out, int out_size)
{
    const float* x    = (const float*)d_in[0];
    const int*   eidx = (const int*)  d_in[1];
    const float* gw[4]  = { (const float*)d_in[2],  (const float*)d_in[6],
                            (const float*)d_in[10], (const float*)d_in[14] };
    const float* gas[4] = { (const float*)d_in[3],  (const float*)d_in[7],
                            (const float*)d_in[11], (const float*)d_in[15] };
    const float* gad[4] = { (const float*)d_in[4],  (const float*)d_in[8],
                            (const float*)d_in[12], (const float*)d_in[16] };
    const float* gb[4]  = { (const float*)d_in[5],  (const float*)d_in[9],
                            (const float*)d_in[13], (const float*)d_in[17] };
    const float* wih0 = (const float*)d_in[18];
    const float* whh0 = (const float*)d_in[19];
    const float* bih0 = (const float*)d_in[20];
    const float* bhh0 = (const float*)d_in[21];
    const float* wih1 = (const float*)d_in[22];
    const float* whh1 = (const float*)d_in[23];
    const float* bih1 = (const float*)d_in[24];
    const float* bhh1 = (const float*)d_in[25];
    const float* attn_w = (const float*)d_in[26];
    const float* attn_b = (const float*)d_in[27];
    const float* fc_w   = (const float*)d_in[28];
    const float* fc_b   = (const float*)d_in[29];
    float* out = (float*)d_out;

    const int smem_attn = ((8 * GROW + 3 * 128 + 4 * 272 + 1296) +
                           (NEDGES * 3 + NNODES + 1 + 4)) * 4;
    const int smem_rec  = (128 * 129 + 8 * 128 + 8 * 32) * 4;

    cudaFuncSetAttribute((const void*)gat_attn,
                         cudaFuncAttributeMaxDynamicSharedMemorySize, smem_attn);
    cudaFuncSetAttribute((const void*)lstm_recur,
                         cudaFuncAttributeMaxDynamicSharedMemorySize, smem_rec);

    const int attn_grid = NG / 8;        // 2048
    const int mm_grid   = MROWS / 128;   // 2176

    // ---- GAT layer 0: x @ W0 -> tmpH -> attn -> bufA (relu)
    gat_mm0<<<(MROWS * 32) / 256, 256>>>(x, gw[0]);
    gat_attn<<<attn_grid, 256, smem_attn>>>(gas[0], gad[0], gb[0], eidx, 0, 1);

    // ---- GAT layer 1: bufA @ W1 -> tmpH -> attn -> bufB
    sgemm128<false><<<dim3(mm_grid, 1), 256>>>(0, gw[1], nullptr, nullptr, 2, MROWS, 128, 128);
    gat_attn<<<attn_grid, 256, smem_attn>>>(gas[1], gad[1], gb[1], eidx, 1, 0);

    // ---- GAT layer 2: bufB @ W2 -> tmpH -> attn -> bufA (relu)
    sgemm128<false><<<dim3(mm_grid, 1), 256>>>(1, gw[2], nullptr, nullptr, 2, MROWS, 128, 128);
    gat_attn<<<attn_grid, 256, smem_attn>>>(gas[2], gad[2], gb[2], eidx, 0, 1);

    // ---- GAT layer 3: bufA @ W3 -> tmpH -> attn -> bufB
    sgemm128<false><<<dim3(mm_grid, 1), 256>>>(0, gw[3], nullptr, nullptr, 2, MROWS, 128, 128);
    gat_attn<<<attn_grid, 256, smem_attn>>>(gas[3], gad[3], gb[3], eidx, 1, 0);

    // ---- LSTM layer 0: pre-gates GEMM (A = bufB viewed [16384, 2176]) + recurrence
    sgemm128<true><<<dim3(NG / 128, GATES / 128), 256>>>(1, wih0, bih0, bhh0, 4, NG, GATES, LSTM_IN);
    lstm_recur<<<dim3(32, 4), 256, smem_rec>>>(whh0, 0);

    // ---- LSTM layer 1: pre-gates GEMM (A = g_h1 [16384,128]) + recurrence
    sgemm128<true><<<dim3(NG / 128, GATES / 128), 256>>>(3, wih1, bih1, bhh1, 4, NG, GATES, HDIM);
    lstm_recur<<<dim3(32, 4), 256, smem_rec>>>(whh1, 1);

    // ---- head
    attn_fc<<<BATCH, 128>>>(attn_w, attn_b, fc_w, fc_b, out);
}

// round 8
// speedup vs baseline: 2.0479x; 1.1803x over previous
#include <cuda_runtime.h>
#include <cuda_bf16.h>

// ----------------------------------------------------------------------------
// Problem constants
// ----------------------------------------------------------------------------
#define BATCH 256
#define SEQ 64
#define NG (BATCH*SEQ)          // 16384 graphs
#define NNODES 17
#define NEDGES 81               // 64 edges + 17 self loops
#define HDIM 128                // HEADS*HID = 2*64
#define GROW (NNODES*HDIM)      // 2176 floats per graph
#define MROWS (NG*NNODES)       // 278528 node rows
#define LSTM_IN 2176
#define GATES 512               // 4*128

// ----------------------------------------------------------------------------
// Scratch (device globals). 16B-aligned.
// ----------------------------------------------------------------------------
__device__ __align__(16) float g_bufA[NG * GROW];
__device__ __align__(16) float g_bufB[NG * GROW];
__device__ __align__(16) float g_tmpH[NG * GROW];
__device__ __align__(16) float g_pre [NG * GATES];
__device__ __align__(16) float g_h1  [NG * HDIM];
__device__ __align__(16) float g_h2  [NG * HDIM];
__device__ __align__(16) float g_hstate[BATCH * HDIM];
__device__ volatile unsigned g_bar_gen;
__device__ unsigned g_bar_cnt;

// bf16 hi/lo weight copies (built by prep kernels each launch)
__device__ __align__(16) __nv_bfloat16 g_w0h[GATES * LSTM_IN];
__device__ __align__(16) __nv_bfloat16 g_w0l[GATES * LSTM_IN];
__device__ __align__(16) __nv_bfloat16 g_w1h[GATES * HDIM];
__device__ __align__(16) __nv_bfloat16 g_w1l[GATES * HDIM];
__device__ __align__(16) __nv_bfloat16 g_gwh[3][HDIM * HDIM];   // transposed [N][K]
__device__ __align__(16) __nv_bfloat16 g_gwl[3][HDIM * HDIM];

__device__ __forceinline__ const float* bufsel_r(int s)
{
    switch (s) {
        case 0: return g_bufA;
        case 1: return g_bufB;
        case 2: return g_tmpH;
        case 3: return g_h1;
        default: return g_pre;
    }
}
__device__ __forceinline__ float* bufsel_w(int s)
{
    switch (s) {
        case 0: return g_bufA;
        case 1: return g_bufB;
        case 2: return g_tmpH;
        default: return g_pre;
    }
}
__device__ __forceinline__ void wsel(int s, const __nv_bfloat16** h, const __nv_bfloat16** l)
{
    switch (s) {
        case 0: *h = g_w0h;   *l = g_w0l;   break;
        case 1: *h = g_w1h;   *l = g_w1l;   break;
        case 2: *h = g_gwh[0]; *l = g_gwl[0]; break;
        case 3: *h = g_gwh[1]; *l = g_gwl[1]; break;
        default: *h = g_gwh[2]; *l = g_gwl[2]; break;
    }
}

// ----------------------------------------------------------------------------
// Grid barrier for the persistent LSTM kernel (128 CTAs < 148 SMs)
// ----------------------------------------------------------------------------
__device__ __forceinline__ void grid_barrier(unsigned nblocks)
{
    __syncthreads();
    if (threadIdx.x == 0) {
        __threadfence();
        unsigned gen = g_bar_gen;
        if (atomicAdd(&g_bar_cnt, 1u) == nblocks - 1u) {
            g_bar_cnt = 0u;
            __threadfence();
            g_bar_gen = gen + 1u;
        } else {
            while (g_bar_gen == gen) { __nanosleep(64); }
        }
    }
    __syncthreads();
}

// ----------------------------------------------------------------------------
// Weight prep: fp32 -> bf16 hi/lo split.
// prep_tn: same layout ([N,K] row-major).  prep_nn_t: [K,N] -> transposed [N,K].
// ----------------------------------------------------------------------------
__device__ __forceinline__ void bf16_split(float x, __nv_bfloat16& h, __nv_bfloat16& l)
{
    h = __float2bfloat16_rn(x);
    l = __float2bfloat16_rn(x - __bfloat162float(h));
}

__global__ void prep_tn(const float* __restrict__ W, int widx, int total)
{
    const __nv_bfloat16 *hc, *lc;
    wsel(widx, &hc, &lc);
    __nv_bfloat16* H = (__nv_bfloat16*)hc;
    __nv_bfloat16* L = (__nv_bfloat16*)lc;
    const int i = blockIdx.x * 256 + threadIdx.x;
    if (i < total) bf16_split(W[i], H[i], L[i]);
}

__global__ void prep_nn_t(const float* __restrict__ W, int widx, int K, int N)
{
    const __nv_bfloat16 *hc, *lc;
    wsel(widx, &hc, &lc);
    __nv_bfloat16* H = (__nv_bfloat16*)hc;
    __nv_bfloat16* L = (__nv_bfloat16*)lc;
    const int i = blockIdx.x * 256 + threadIdx.x;
    if (i < K * N) {
        const int k = i / N, n = i % N;
        bf16_split(W[i], H[n * K + k], L[n * K + k]);
    }
}

// ----------------------------------------------------------------------------
// Layer-0 projection: H0[row,128] = x[row,0:3] @ W0[3,128]
// ----------------------------------------------------------------------------
__global__ void gat_mm0(const float* __restrict__ x, const float* __restrict__ W)
{
    __shared__ float sW[3 * 128];
    const int tid = threadIdx.x;
    for (int i = tid; i < 3 * 128; i += 256) sW[i] = W[i];
    __syncthreads();

    const long i = (long)blockIdx.x * 256 + tid;
    const long row = i >> 5;
    const int q = ((int)(i & 31)) << 2;
    const float x0 = x[row * 3 + 0];
    const float x1 = x[row * 3 + 1];
    const float x2 = x[row * 3 + 2];
    const float4 w0 = *(const float4*)&sW[0 * 128 + q];
    const float4 w1 = *(const float4*)&sW[1 * 128 + q];
    const float4 w2 = *(const float4*)&sW[2 * 128 + q];
    float4 o;
    o.x = x0 * w0.x + x1 * w1.x + x2 * w2.x;
    o.y = x0 * w0.y + x1 * w1.y + x2 * w2.y;
    o.z = x0 * w0.z + x1 * w1.z + x2 * w2.z;
    o.w = x0 * w0.w + x1 * w1.w + x2 * w2.w;
    *(float4*)&g_tmpH[row * 128 + q] = o;
}

// ----------------------------------------------------------------------------
// Tensor-core GEMM: C[M,Nn] = A[M,K] @ B^T  (B given as [Nn,K] bf16 hi/lo).
// 3-term bf16 split: D += Ah*Bh + Ah*Bl + Al*Bh  (fp32 accumulate).
// CTA 128x128, 8 warps (4m x 2n), warp tile 32x64, mma.m16n8k16, BK=32.
// ----------------------------------------------------------------------------
__device__ __forceinline__ void mma_bf16(float* c, const unsigned* a, unsigned b0, unsigned b1)
{
    asm volatile(
        "mma.sync.aligned.m16n8k16.row.col.f32.bf16.bf16.f32 "
        "{%0,%1,%2,%3}, {%4,%5,%6,%7}, {%8,%9}, {%0,%1,%2,%3};"
        : "+f"(c[0]), "+f"(c[1]), "+f"(c[2]), "+f"(c[3])
        : "r"(a[0]), "r"(a[1]), "r"(a[2]), "r"(a[3]), "r"(b0), "r"(b1));
}

template<bool BIAS>
__global__ void __launch_bounds__(256)
bgemm(int a_sel, int widx,
      const float* __restrict__ bias1, const float* __restrict__ bias2,
      int out_sel, int M, int Nn, int K)
{
    const float* A = bufsel_r(a_sel);
    float* C = bufsel_w(out_sel);
    const __nv_bfloat16 *Bh_g, *Bl_g;
    wsel(widx, &Bh_g, &Bl_g);

    // stride 40 bf16 per row: conflict-free fragment reads
    __shared__ __align__(16) __nv_bfloat16 Ah[128][40];
    __shared__ __align__(16) __nv_bfloat16 Al[128][40];
    __shared__ __align__(16) __nv_bfloat16 Bh[128][40];
    __shared__ __align__(16) __nv_bfloat16 Bl[128][40];

    const int tid  = threadIdx.x;
    const int warp = tid >> 5;
    const int lane = tid & 31;
    const int g    = lane >> 2;     // group id 0..7
    const int tig  = lane & 3;      // thread-in-group

    const int bm = blockIdx.x * 128;
    const int bn = blockIdx.y * 128;
    const int m0 = (warp >> 1) * 32;    // warp m offset (0,32,64,96)
    const int n0 = (warp & 1) * 64;     // warp n offset (0,64)

    float acc[2][8][4];
    #pragma unroll
    for (int mt = 0; mt < 2; mt++)
        #pragma unroll
        for (int nt = 0; nt < 8; nt++)
            #pragma unroll
            for (int r = 0; r < 4; r++) acc[mt][nt][r] = 0.f;

    // staging mapping: thread -> (row tid>>1, 16-elem half (tid&1))
    const int ar  = tid >> 1;
    const int akq = (tid & 1) << 4;
    const float* Aptr = A + (long)(bm + ar) * K + akq;
    const __nv_bfloat16* Bhp = Bh_g + (long)(bn + ar) * K + akq;
    const __nv_bfloat16* Blp = Bl_g + (long)(bn + ar) * K + akq;

    for (int k0 = 0; k0 < K; k0 += 32) {
        __syncthreads();
        // stage A (fp32 -> hi/lo bf16)
        {
            float4 v0 = *(const float4*)(Aptr + k0);
            float4 v1 = *(const float4*)(Aptr + k0 + 4);
            float4 v2 = *(const float4*)(Aptr + k0 + 8);
            float4 v3 = *(const float4*)(Aptr + k0 + 12);
            float vf[16] = { v0.x,v0.y,v0.z,v0.w, v1.x,v1.y,v1.z,v1.w,
                             v2.x,v2.y,v2.z,v2.w, v3.x,v3.y,v3.z,v3.w };
            #pragma unroll
            for (int p = 0; p < 8; p++) {
                __nv_bfloat16 h0, l0, h1, l1;
                bf16_split(vf[2*p],     h0, l0);
                bf16_split(vf[2*p + 1], h1, l1);
                __nv_bfloat162 th; th.x = h0; th.y = h1;
                __nv_bfloat162 tl; tl.x = l0; tl.y = l1;
                *(__nv_bfloat162*)&Ah[ar][akq + 2*p] = th;
                *(__nv_bfloat162*)&Al[ar][akq + 2*p] = tl;
            }
            // stage B (straight bf16 copy, [N,K] layout)
            *(uint4*)&Bh[ar][akq]     = *(const uint4*)(Bhp + k0);
            *(uint4*)&Bh[ar][akq + 8] = *(const uint4*)(Bhp + k0 + 8);
            *(uint4*)&Bl[ar][akq]     = *(const uint4*)(Blp + k0);
            *(uint4*)&Bl[ar][akq + 8] = *(const uint4*)(Blp + k0 + 8);
        }
        __syncthreads();

        #pragma unroll
        for (int kk = 0; kk < 32; kk += 16) {
            unsigned ah[2][4], al[2][4];
            #pragma unroll
            for (int mt = 0; mt < 2; mt++) {
                const int r = m0 + mt * 16 + g;
                ah[mt][0] = *(const unsigned*)&Ah[r][kk + 2*tig];
                ah[mt][1] = *(const unsigned*)&Ah[r + 8][kk + 2*tig];
                ah[mt][2] = *(const unsigned*)&Ah[r][kk + 8 + 2*tig];
                ah[mt][3] = *(const unsigned*)&Ah[r + 8][kk + 8 + 2*tig];
                al[mt][0] = *(const unsigned*)&Al[r][kk + 2*tig];
                al[mt][1] = *(const unsigned*)&Al[r + 8][kk + 2*tig];
                al[mt][2] = *(const unsigned*)&Al[r][kk + 8 + 2*tig];
                al[mt][3] = *(const unsigned*)&Al[r + 8][kk + 8 + 2*tig];
            }
            #pragma unroll
            for (int nt = 0; nt < 8; nt++) {
                const int rn = n0 + nt * 8 + g;
                const unsigned bh0 = *(const unsigned*)&Bh[rn][kk + 2*tig];
                const unsigned bh1 = *(const unsigned*)&Bh[rn][kk + 8 + 2*tig];
                const unsigned bl0 = *(const unsigned*)&Bl[rn][kk + 2*tig];
                const unsigned bl1 = *(const unsigned*)&Bl[rn][kk + 8 + 2*tig];
                #pragma unroll
                for (int mt = 0; mt < 2; mt++) {
                    mma_bf16(acc[mt][nt], ah[mt], bh0, bh1);
                    mma_bf16(acc[mt][nt], ah[mt], bl0, bl1);
                    mma_bf16(acc[mt][nt], al[mt], bh0, bh1);
                }
            }
        }
    }

    // epilogue
    #pragma unroll
    for (int mt = 0; mt < 2; mt++) {
        const long row = bm + m0 + mt * 16 + g;
        #pragma unroll
        for (int nt = 0; nt < 8; nt++) {
            const int col = bn + n0 + nt * 8 + 2 * tig;
            float c0 = acc[mt][nt][0], c1 = acc[mt][nt][1];
            float c2 = acc[mt][nt][2], c3 = acc[mt][nt][3];
            if (BIAS) {
                const float b0 = bias1[col]     + bias2[col];
                const float b1 = bias1[col + 1] + bias2[col + 1];
                c0 += b0; c1 += b1; c2 += b0; c3 += b1;
            }
            *(float2*)&C[row * Nn + col]       = make_float2(c0, c1);
            *(float2*)&C[(row + 8) * Nn + col] = make_float2(c2, c3);
        }
    }
}

// ----------------------------------------------------------------------------
// GAT attention + aggregation (proven R3 version, 226.6us/layer).
// ----------------------------------------------------------------------------
__global__ void gat_attn(const float* __restrict__ a_src, const float* __restrict__ a_dst,
                         const float* __restrict__ bias, const int* __restrict__ edge_index,
                         int out_sel, int relu_flag)
{
    extern __shared__ __align__(16) float smem[];
    float* sH   = smem;                    // 8*2176
    float* sAs  = sH  + 8 * GROW;
    float* sAd  = sAs + 128;
    float* sB   = sAd + 128;
    float* s_as = sB  + 128;               // 8*34
    float* s_ad = s_as + 272;
    float* s_m  = s_ad + 272;
    float* s_dn = s_m  + 272;
    float* s_ev = s_dn + 272;              // 8*162
    int*   s_src = (int*)(s_ev + 1296);
    int*   s_dst = s_src + NEDGES;
    int*   s_cs  = s_dst + NEDGES;
    int*   s_ce  = s_cs + NNODES + 1;

    const int tid = threadIdx.x;

    if (tid == 0) {
        int cnt[NNODES];
        for (int n = 0; n < NNODES; n++) cnt[n] = 0;
        for (int e = 0; e < NEDGES; e++) {
            int s = (e < 64) ? edge_index[e]      : (e - 64);
            int d = (e < 64) ? edge_index[64 + e] : (e - 64);
            s_src[e] = s; s_dst[e] = d; cnt[d]++;
        }
        int off = 0;
        for (int n = 0; n < NNODES; n++) { s_cs[n] = off; off += cnt[n]; cnt[n] = s_cs[n]; }
        s_cs[NNODES] = off;
        for (int e = 0; e < NEDGES; e++) s_ce[cnt[s_dst[e]]++] = e;
    }
    if (tid < 128) { sAs[tid] = a_src[tid]; sAd[tid] = a_dst[tid]; sB[tid] = bias[tid]; }

    const float* Hsrc = g_tmpH + (long)blockIdx.x * (8 * GROW);
    for (int i = tid; i < (8 * GROW) / 4; i += 256)
        *(float4*)&sH[i * 4] = *(const float4*)&Hsrc[i * 4];
    __syncthreads();

    for (int i = tid; i < 8 * 64; i += 256) {
        const int g = i >> 6, t = i & 63;
        if (t < 34) {
            const int n = t >> 1, hh = t & 1;
            const float* hp = &sH[g * GROW + n * 128 + hh * 64];
            float as = 0.f, ad = 0.f;
            #pragma unroll 8
            for (int d = 0; d < 64; d++) {
                as += hp[d] * sAs[hh * 64 + d];
                ad += hp[d] * sAd[hh * 64 + d];
            }
            s_as[g * 34 + t] = as; s_ad[g * 34 + t] = ad;
        }
    }
    __syncthreads();

    for (int i = tid; i < 8 * 256; i += 256) {
        const int g = i >> 8, t = i & 255;
        if (t < 162) {
            const int e = t >> 1, hh = t & 1;
            const float raw = s_as[g * 34 + s_src[e] * 2 + hh]
                            + s_ad[g * 34 + s_dst[e] * 2 + hh];
            s_ev[g * 162 + t] = raw > 0.f ? raw : 0.2f * raw;
        }
    }
    __syncthreads();

    for (int i = tid; i < 8 * 64; i += 256) {
        const int g = i >> 6, t = i & 63;
        if (t < 34) {
            const int n = t >> 1, hh = t & 1;
            float m = -1e30f;
            for (int p = s_cs[n]; p < s_cs[n + 1]; p++)
                m = fmaxf(m, s_ev[g * 162 + s_ce[p] * 2 + hh]);
            float den = 0.f;
            for (int p = s_cs[n]; p < s_cs[n + 1]; p++)
                den += __expf(s_ev[g * 162 + s_ce[p] * 2 + hh] - m);
            s_m[g * 34 + t] = m; s_dn[g * 34 + t] = den;
        }
    }
    __syncthreads();

    for (int i = tid; i < 8 * 256; i += 256) {
        const int g = i >> 8, t = i & 255;
        if (t < 162) {
            const int e = t >> 1, hh = t & 1;
            const int d = s_dst[e];
            s_ev[g * 162 + t] = __expf(s_ev[g * 162 + t] - s_m[g * 34 + d * 2 + hh])
                                / (s_dn[g * 34 + d * 2 + hh] + 1e-16f);
        }
    }
    __syncthreads();

    float* outb = bufsel_w(out_sel);
    for (int i = tid; i < 8 * NNODES * 32; i += 256) {
        const int g = i / (NNODES * 32);
        const int r = i - g * (NNODES * 32);
        const int n = r >> 5;
        const int q = (r & 31) << 2;
        const int hh = q >> 6;
        float4 acc = make_float4(0.f, 0.f, 0.f, 0.f);
        for (int p = s_cs[n]; p < s_cs[n + 1]; p++) {
            const int e = s_ce[p];
            const float al = s_ev[g * 162 + e * 2 + hh];
            const float4 hv = *(const float4*)&sH[g * GROW + s_src[e] * 128 + q];
            acc.x += al * hv.x; acc.y += al * hv.y;
            acc.z += al * hv.z; acc.w += al * hv.w;
        }
        const float4 b4 = *(const float4*)&sB[q];
        acc.x += b4.x; acc.y += b4.y; acc.z += b4.z; acc.w += b4.w;
        if (relu_flag) {
            acc.x = fmaxf(acc.x, 0.f); acc.y = fmaxf(acc.y, 0.f);
            acc.z = fmaxf(acc.z, 0.f); acc.w = fmaxf(acc.w, 0.f);
        }
        *(float4*)&outb[((long)blockIdx.x * 8 + g) * GROW + n * 128 + q] = acc;
    }
}

// ----------------------------------------------------------------------------
// LSTM recurrence (persistent, 128 CTAs) — proven R3 version.
// ----------------------------------------------------------------------------
__global__ void lstm_recur(const float* __restrict__ whh, int out_sel)
{
    extern __shared__ __align__(16) float smem[];
    float* sW = smem;              // 128*129
    float* sH = sW + 128 * 129;    // 8*128
    float* sC = sH + 8 * 128;      // 8*32

    float* hseq = (out_sel == 0) ? g_h1 : g_h2;
    const float* pre = g_pre;

    const int tid = threadIdx.x;
    const int b0 = blockIdx.x * 8;
    const int d0 = blockIdx.y * 32;
    const unsigned nblocks = gridDim.x * gridDim.y;

    for (int i = tid; i < 128 * 128; i += blockDim.x) {
        const int r = i >> 7, k = i & 127;
        const int j = ((r >> 5) << 7) + d0 + (r & 31);
        sW[r * 129 + k] = whh[j * 128 + k];
    }
    {
        const int row = tid >> 5, l = tid & 31;
        sC[row * 32 + l] = 0.f;
        g_hstate[(b0 + row) * 128 + d0 + l] = 0.f;
    }
    grid_barrier(nblocks);

    for (int t = 0; t < SEQ; t++) {
        for (int i = tid; i < 8 * 128; i += blockDim.x) {
            const int row = i >> 7, k = i & 127;
            sH[i] = __ldcg(&g_hstate[(b0 + row) * 128 + k]);
        }
        __syncthreads();

        {
            const int row = tid >> 5, l = tid & 31;
            const float* hp = &sH[row * 128];
            const float* w0 = &sW[(l)      * 129];
            const float* w1 = &sW[(32 + l) * 129];
            const float* w2 = &sW[(64 + l) * 129];
            const float* w3 = &sW[(96 + l) * 129];
            const long pbase = ((long)(b0 + row) * SEQ + t) * GATES;
            float a0 = pre[pbase +       d0 + l];
            float a1 = pre[pbase + 128 + d0 + l];
            float a2 = pre[pbase + 256 + d0 + l];
            float a3 = pre[pbase + 384 + d0 + l];
            #pragma unroll 4
            for (int k = 0; k < 128; k++) {
                const float hv = hp[k];
                a0 += hv * w0[k]; a1 += hv * w1[k];
                a2 += hv * w2[k]; a3 += hv * w3[k];
            }
            const float ig = 1.f / (1.f + expf(-a0));
            const float fg = 1.f / (1.f + expf(-a1));
            const float gg = tanhf(a2);
            const float og = 1.f / (1.f + expf(-a3));
            const float c = fg * sC[row * 32 + l] + ig * gg;
            sC[row * 32 + l] = c;
            const float h = og * tanhf(c);
            g_hstate[(b0 + row) * 128 + d0 + l] = h;
            hseq[((long)(b0 + row) * SEQ + t) * 128 + d0 + l] = h;
        }
        grid_barrier(nblocks);
    }
}

// ----------------------------------------------------------------------------
// Temporal attention + FC head. One CTA (128 threads) per batch row.
// ----------------------------------------------------------------------------
__global__ void attn_fc(const float* __restrict__ attn_w, const float* __restrict__ attn_b,
                        const float* __restrict__ fc_w,   const float* __restrict__ fc_b,
                        float* __restrict__ out)
{
    __shared__ float sw[128];
    __shared__ float sc[SEQ];
    __shared__ float sctx[128];

    const int b = blockIdx.x, tid = threadIdx.x;
    const float* h2 = g_h2 + (long)b * SEQ * 128;

    sw[tid] = attn_w[tid];
    __syncthreads();

    if (tid < SEQ) {
        const float* hp = h2 + tid * 128;
        float acc = attn_b[0];
        #pragma unroll 8
        for (int k = 0; k < 128; k++) acc += hp[k] * sw[k];
        sc[tid] = tanhf(acc);
    }
    __syncthreads();

    if (tid == 0) {
        float m = -1e30f;
        for (int t = 0; t < SEQ; t++) m = fmaxf(m, sc[t]);
        float s = 0.f;
        for (int t = 0; t < SEQ; t++) { sc[t] = __expf(sc[t] - m); s += sc[t]; }
        const float inv = 1.f / s;
        for (int t = 0; t < SEQ; t++) sc[t] *= inv;
    }
    __syncthreads();

    {
        float acc = 0.f;
        for (int t = 0; t < SEQ; t++) acc += sc[t] * h2[t * 128 + tid];
        sctx[tid] = acc;
    }
    __syncthreads();

    if (tid < 10) {
        float acc = fc_b[tid];
        #pragma unroll 8
        for (int k = 0; k < 128; k++) acc += sctx[k] * fc_w[tid * 128 + k];
        out[b * 10 + tid] = acc;
    }
}

// ----------------------------------------------------------------------------
// Launcher
// ----------------------------------------------------------------------------
extern "C" void kernel_launch(void* const* d_in, const int* in_sizes, int n_in,
                              void* d_out, int out_size)
{
    const float* x    = (const float*)d_in[0];
    const int*   eidx = (const int*)  d_in[1];
    const float* gw[4]  = { (const float*)d_in[2],  (const float*)d_in[6],
                            (const float*)d_in[10], (const float*)d_in[14] };
    const float* gas[4] = { (const float*)d_in[3],  (const float*)d_in[7],
                            (const float*)d_in[11], (const float*)d_in[15] };
    const float* gad[4] = { (const float*)d_in[4],  (const float*)d_in[8],
                            (const float*)d_in[12], (const float*)d_in[16] };
    const float* gb[4]  = { (const float*)d_in[5],  (const float*)d_in[9],
                            (const float*)d_in[13], (const float*)d_in[17] };
    const float* wih0 = (const float*)d_in[18];
    const float* whh0 = (const float*)d_in[19];
    const float* bih0 = (const float*)d_in[20];
    const float* bhh0 = (const float*)d_in[21];
    const float* wih1 = (const float*)d_in[22];
    const float* whh1 = (const float*)d_in[23];
    const float* bih1 = (const float*)d_in[24];
    const float* bhh1 = (const float*)d_in[25];
    const float* attn_w = (const float*)d_in[26];
    const float* attn_b = (const float*)d_in[27];
    const float* fc_w   = (const float*)d_in[28];
    const float* fc_b   = (const float*)d_in[29];
    float* out = (float*)d_out;

    const int smem_attn = ((8 * GROW + 3 * 128 + 4 * 272 + 1296) +
                           (NEDGES * 3 + NNODES + 1 + 4)) * 4;
    const int smem_rec  = (128 * 129 + 8 * 128 + 8 * 32) * 4;

    cudaFuncSetAttribute((const void*)gat_attn,
                         cudaFuncAttributeMaxDynamicSharedMemorySize, smem_attn);
    cudaFuncSetAttribute((const void*)lstm_recur,
                         cudaFuncAttributeMaxDynamicSharedMemorySize, smem_rec);

    const int attn_grid = NG / 8;        // 2048
    const int mm_grid   = MROWS / 128;   // 2176

    // weight prep (bf16 hi/lo)
    prep_tn  <<<(GATES * LSTM_IN + 255) / 256, 256>>>(wih0, 0, GATES * LSTM_IN);
    prep_tn  <<<(GATES * HDIM    + 255) / 256, 256>>>(wih1, 1, GATES * HDIM);
    prep_nn_t<<<(HDIM * HDIM     + 255) / 256, 256>>>(gw[1], 2, HDIM, HDIM);
    prep_nn_t<<<(HDIM * HDIM     + 255) / 256, 256>>>(gw[2], 3, HDIM, HDIM);
    prep_nn_t<<<(HDIM * HDIM     + 255) / 256, 256>>>(gw[3], 4, HDIM, HDIM);

    // ---- GAT layer 0: x @ W0 -> tmpH -> attn -> bufA (relu)
    gat_mm0<<<(MROWS * 32) / 256, 256>>>(x, gw[0]);
    gat_attn<<<attn_grid, 256, smem_attn>>>(gas[0], gad[0], gb[0], eidx, 0, 1);

    // ---- GAT layer 1: bufA @ W1 -> tmpH -> attn -> bufB
    bgemm<false><<<dim3(mm_grid, 1), 256>>>(0, 2, nullptr, nullptr, 2, MROWS, 128, 128);
    gat_attn<<<attn_grid, 256, smem_attn>>>(gas[1], gad[1], gb[1], eidx, 1, 0);

    // ---- GAT layer 2: bufB @ W2 -> tmpH -> attn -> bufA (relu)
    bgemm<false><<<dim3(mm_grid, 1), 256>>>(1, 3, nullptr, nullptr, 2, MROWS, 128, 128);
    gat_attn<<<attn_grid, 256, smem_attn>>>(gas[2], gad[2], gb[2], eidx, 0, 1);

    // ---- GAT layer 3: bufA @ W3 -> tmpH -> attn -> bufB
    bgemm<false><<<dim3(mm_grid, 1), 256>>>(0, 4, nullptr, nullptr, 2, MROWS, 128, 128);
    gat_attn<<<attn_grid, 256, smem_attn>>>(gas[3], gad[3], gb[3], eidx, 1, 0);

    // ---- LSTM layer 0: pre-gates GEMM (A = bufB viewed [16384, 2176]) + recurrence
    bgemm<true><<<dim3(NG / 128, GATES / 128), 256>>>(1, 0, bih0, bhh0, 4, NG, GATES, LSTM_IN);
    lstm_recur<<<dim3(32, 4), 256, smem_rec>>>(whh0, 0);

    // ---- LSTM layer 1: pre-gates GEMM (A = g_h1 [16384,128]) + recurrence
    bgemm<true><<<dim3(NG / 128, GATES / 128), 256>>>(3, 1, bih1, bhh1, 4, NG, GATES, HDIM);
    lstm_recur<<<dim3(32, 4), 256, smem_rec>>>(whh1, 1);

    // ---- head
    attn_fc<<<BATCH, 128>>>(attn_w, attn_b, fc_w, fc_b, out);
}

// round 10
// speedup vs baseline: 2.2174x; 1.0828x over previous
#include <cuda_runtime.h>
#include <cuda_bf16.h>

// ----------------------------------------------------------------------------
// Problem constants
// ----------------------------------------------------------------------------
#define BATCH 256
#define SEQ 64
#define NG (BATCH*SEQ)          // 16384 graphs
#define NNODES 17
#define NEDGES 81               // 64 edges + 17 self loops
#define HDIM 128                // HEADS*HID = 2*64
#define GROW (NNODES*HDIM)      // 2176 floats per graph
#define MROWS (NG*NNODES)       // 278528 node rows
#define LSTM_IN 2176
#define GATES 512               // 4*128

// ----------------------------------------------------------------------------
// Scratch (device globals). 16B-aligned.
// ----------------------------------------------------------------------------
__device__ __align__(16) float g_bufA[NG * GROW];
__device__ __align__(16) float g_bufB[NG * GROW];
__device__ __align__(16) float g_tmpH[NG * GROW];
__device__ __align__(16) float g_pre [NG * GATES];
__device__ __align__(16) float g_h1  [NG * HDIM];
__device__ __align__(16) float g_h2  [NG * HDIM];
__device__ __align__(16) float g_hstate[BATCH * HDIM];
__device__ volatile unsigned g_bar_gen;
__device__ unsigned g_bar_cnt;

// bf16 hi/lo weight copies (built by prep kernels each launch)
__device__ __align__(16) __nv_bfloat16 g_w0h[GATES * LSTM_IN];
__device__ __align__(16) __nv_bfloat16 g_w0l[GATES * LSTM_IN];
__device__ __align__(16) __nv_bfloat16 g_w1h[GATES * HDIM];
__device__ __align__(16) __nv_bfloat16 g_w1l[GATES * HDIM];
__device__ __align__(16) __nv_bfloat16 g_gwh[3][HDIM * HDIM];   // transposed [N][K]
__device__ __align__(16) __nv_bfloat16 g_gwl[3][HDIM * HDIM];

__device__ __forceinline__ const float* bufsel_r(int s)
{
    switch (s) {
        case 0: return g_bufA;
        case 1: return g_bufB;
        case 2: return g_tmpH;
        case 3: return g_h1;
        default: return g_pre;
    }
}
__device__ __forceinline__ float* bufsel_w(int s)
{
    switch (s) {
        case 0: return g_bufA;
        case 1: return g_bufB;
        case 2: return g_tmpH;
        default: return g_pre;
    }
}
__device__ __forceinline__ void wsel(int s, const __nv_bfloat16** h, const __nv_bfloat16** l)
{
    switch (s) {
        case 0: *h = g_w0h;   *l = g_w0l;   break;
        case 1: *h = g_w1h;   *l = g_w1l;   break;
        case 2: *h = g_gwh[0]; *l = g_gwl[0]; break;
        case 3: *h = g_gwh[1]; *l = g_gwl[1]; break;
        default: *h = g_gwh[2]; *l = g_gwl[2]; break;
    }
}

// ----------------------------------------------------------------------------
// Grid barrier for the persistent LSTM kernel (128 CTAs < 148 SMs)
// ----------------------------------------------------------------------------
__device__ __forceinline__ void grid_barrier(unsigned nblocks)
{
    __syncthreads();
    if (threadIdx.x == 0) {
        __threadfence();
        unsigned gen = g_bar_gen;
        if (atomicAdd(&g_bar_cnt, 1u) == nblocks - 1u) {
            g_bar_cnt = 0u;
            __threadfence();
            g_bar_gen = gen + 1u;
        } else {
            while (g_bar_gen == gen) { __nanosleep(64); }
        }
    }
    __syncthreads();
}

// ----------------------------------------------------------------------------
// Weight prep: fp32 -> bf16 hi/lo split.
// ----------------------------------------------------------------------------
__device__ __forceinline__ void bf16_split(float x, __nv_bfloat16& h, __nv_bfloat16& l)
{
    h = __float2bfloat16_rn(x);
    l = __float2bfloat16_rn(x - __bfloat162float(h));
}

__global__ void prep_tn(const float* __restrict__ W, int widx, int total)
{
    const __nv_bfloat16 *hc, *lc;
    wsel(widx, &hc, &lc);
    __nv_bfloat16* H = (__nv_bfloat16*)hc;
    __nv_bfloat16* L = (__nv_bfloat16*)lc;
    const int i = blockIdx.x * 256 + threadIdx.x;
    if (i < total) bf16_split(W[i], H[i], L[i]);
}

__global__ void prep_nn_t(const float* __restrict__ W, int widx, int K, int N)
{
    const __nv_bfloat16 *hc, *lc;
    wsel(widx, &hc, &lc);
    __nv_bfloat16* H = (__nv_bfloat16*)hc;
    __nv_bfloat16* L = (__nv_bfloat16*)lc;
    const int i = blockIdx.x * 256 + threadIdx.x;
    if (i < K * N) {
        const int k = i / N, n = i % N;
        bf16_split(W[i], H[n * K + k], L[n * K + k]);
    }
}

// ----------------------------------------------------------------------------
// Layer-0 projection: H0[row,128] = x[row,0:3] @ W0[3,128]
// ----------------------------------------------------------------------------
__global__ void gat_mm0(const float* __restrict__ x, const float* __restrict__ W)
{
    __shared__ float sW[3 * 128];
    const int tid = threadIdx.x;
    for (int i = tid; i < 3 * 128; i += 256) sW[i] = W[i];
    __syncthreads();

    const long i = (long)blockIdx.x * 256 + tid;
    const long row = i >> 5;
    const int q = ((int)(i & 31)) << 2;
    const float x0 = x[row * 3 + 0];
    const float x1 = x[row * 3 + 1];
    const float x2 = x[row * 3 + 2];
    const float4 w0 = *(const float4*)&sW[0 * 128 + q];
    const float4 w1 = *(const float4*)&sW[1 * 128 + q];
    const float4 w2 = *(const float4*)&sW[2 * 128 + q];
    float4 o;
    o.x = x0 * w0.x + x1 * w1.x + x2 * w2.x;
    o.y = x0 * w0.y + x1 * w1.y + x2 * w2.y;
    o.z = x0 * w0.z + x1 * w1.z + x2 * w2.z;
    o.w = x0 * w0.w + x1 * w1.w + x2 * w2.w;
    *(float4*)&g_tmpH[row * 128 + q] = o;
}

// ----------------------------------------------------------------------------
// Tensor-core GEMM: C[M,Nn] = A[M,K] @ B^T  (B given as [Nn,K] bf16 hi/lo).
// 3-term bf16 split: D += Ah*Bh + Ah*Bl + Al*Bh  (fp32 accumulate).
// CTA 128x128, 8 warps, warp tile 32x64, mma.m16n8k16, BK=32.
// PIPELINED: register prefetch of next tile + double smem buffers,
// one __syncthreads per k-tile.
// ----------------------------------------------------------------------------
__device__ __forceinline__ void mma_bf16(float* c, const unsigned* a, unsigned b0, unsigned b1)
{
    asm volatile(
        "mma.sync.aligned.m16n8k16.row.col.f32.bf16.bf16.f32 "
        "{%0,%1,%2,%3}, {%4,%5,%6,%7}, {%8,%9}, {%0,%1,%2,%3};"
        : "+f"(c[0]), "+f"(c[1]), "+f"(c[2]), "+f"(c[3])
        : "r"(a[0]), "r"(a[1]), "r"(a[2]), "r"(a[3]), "r"(b0), "r"(b1));
}

#define BG_STRIDE 40
#define BG_MAT    (128 * BG_STRIDE)     // bf16 elems per matrix per buffer

template<bool BIAS>
__global__ void __launch_bounds__(256)
bgemm(int a_sel, int widx,
      const float* __restrict__ bias1, const float* __restrict__ bias2,
      int out_sel, int M, int Nn, int K)
{
    const float* A = bufsel_r(a_sel);
    float* C = bufsel_w(out_sel);
    const __nv_bfloat16 *Bh_g, *Bl_g;
    wsel(widx, &Bh_g, &Bl_g);

    extern __shared__ __align__(16) __nv_bfloat16 smb[];
    // layout per buffer: Ah, Al, Bh, Bl (each 128 x BG_STRIDE)

    const int tid  = threadIdx.x;
    const int warp = tid >> 5;
    const int lane = tid & 31;
    const int g    = lane >> 2;
    const int tig  = lane & 3;

    const int bm = blockIdx.x * 128;
    const int bn = blockIdx.y * 128;
    const int m0 = (warp >> 1) * 32;
    const int n0 = (warp & 1) * 64;

    float acc[2][8][4];
    #pragma unroll
    for (int mt = 0; mt < 2; mt++)
        #pragma unroll
        for (int nt = 0; nt < 8; nt++)
            #pragma unroll
            for (int r = 0; r < 4; r++) acc[mt][nt][r] = 0.f;

    const int ar  = tid >> 1;
    const int akq = (tid & 1) << 4;
    const float* Aptr = A + (long)(bm + ar) * K + akq;
    const __nv_bfloat16* Bhp = Bh_g + (long)(bn + ar) * K + akq;
    const __nv_bfloat16* Blp = Bl_g + (long)(bn + ar) * K + akq;

    const int NT = K >> 5;

    float4 pv[4];
    uint4  pbh[2], pbl[2];

    // prefetch tile 0
    {
        pv[0] = *(const float4*)(Aptr);
        pv[1] = *(const float4*)(Aptr + 4);
        pv[2] = *(const float4*)(Aptr + 8);
        pv[3] = *(const float4*)(Aptr + 12);
        pbh[0] = *(const uint4*)(Bhp);
        pbh[1] = *(const uint4*)(Bhp + 8);
        pbl[0] = *(const uint4*)(Blp);
        pbl[1] = *(const uint4*)(Blp + 8);
    }

    // store tile 0 into buffer 0
    {
        __nv_bfloat16* Ah = smb;
        __nv_bfloat16* Al = smb + BG_MAT;
        __nv_bfloat16* Bh = smb + 2 * BG_MAT;
        __nv_bfloat16* Bl = smb + 3 * BG_MAT;
        const float vf[16] = { pv[0].x,pv[0].y,pv[0].z,pv[0].w,
                               pv[1].x,pv[1].y,pv[1].z,pv[1].w,
                               pv[2].x,pv[2].y,pv[2].z,pv[2].w,
                               pv[3].x,pv[3].y,pv[3].z,pv[3].w };
        #pragma unroll
        for (int p = 0; p < 8; p++) {
            __nv_bfloat16 h0, l0, h1, l1;
            bf16_split(vf[2*p],     h0, l0);
            bf16_split(vf[2*p + 1], h1, l1);
            __nv_bfloat162 th; th.x = h0; th.y = h1;
            __nv_bfloat162 tl; tl.x = l0; tl.y = l1;
            *(__nv_bfloat162*)&Ah[ar * BG_STRIDE + akq + 2*p] = th;
            *(__nv_bfloat162*)&Al[ar * BG_STRIDE + akq + 2*p] = tl;
        }
        *(uint4*)&Bh[ar * BG_STRIDE + akq]     = pbh[0];
        *(uint4*)&Bh[ar * BG_STRIDE + akq + 8] = pbh[1];
        *(uint4*)&Bl[ar * BG_STRIDE + akq]     = pbl[0];
        *(uint4*)&Bl[ar * BG_STRIDE + akq + 8] = pbl[1];
    }
    __syncthreads();

    int cur = 0;
    for (int kt = 0; kt < NT; kt++) {
        // prefetch next tile into registers (overlaps with compute below)
        if (kt + 1 < NT) {
            const long ko = (long)(kt + 1) * 32;
            pv[0] = *(const float4*)(Aptr + ko);
            pv[1] = *(const float4*)(Aptr + ko + 4);
            pv[2] = *(const float4*)(Aptr + ko + 8);
            pv[3] = *(const float4*)(Aptr + ko + 12);
            pbh[0] = *(const uint4*)(Bhp + ko);
            pbh[1] = *(const uint4*)(Bhp + ko + 8);
            pbl[0] = *(const uint4*)(Blp + ko);
            pbl[1] = *(const uint4*)(Blp + ko + 8);
        }

        // compute current buffer
        {
            const __nv_bfloat16* Ah = smb + cur * 4 * BG_MAT;
            const __nv_bfloat16* Al = Ah + BG_MAT;
            const __nv_bfloat16* Bh = Ah + 2 * BG_MAT;
            const __nv_bfloat16* Bl = Ah + 3 * BG_MAT;

            #pragma unroll
            for (int kk = 0; kk < 32; kk += 16) {
                unsigned ah[2][4], al[2][4];
                #pragma unroll
                for (int mt = 0; mt < 2; mt++) {
                    const int r = m0 + mt * 16 + g;
                    ah[mt][0] = *(const unsigned*)&Ah[r * BG_STRIDE + kk + 2*tig];
                    ah[mt][1] = *(const unsigned*)&Ah[(r + 8) * BG_STRIDE + kk + 2*tig];
                    ah[mt][2] = *(const unsigned*)&Ah[r * BG_STRIDE + kk + 8 + 2*tig];
                    ah[mt][3] = *(const unsigned*)&Ah[(r + 8) * BG_STRIDE + kk + 8 + 2*tig];
                    al[mt][0] = *(const unsigned*)&Al[r * BG_STRIDE + kk + 2*tig];
                    al[mt][1] = *(const unsigned*)&Al[(r + 8) * BG_STRIDE + kk + 2*tig];
                    al[mt][2] = *(const unsigned*)&Al[r * BG_STRIDE + kk + 8 + 2*tig];
                    al[mt][3] = *(const unsigned*)&Al[(r + 8) * BG_STRIDE + kk + 8 + 2*tig];
                }
                #pragma unroll
                for (int nt = 0; nt < 8; nt++) {
                    const int rn = n0 + nt * 8 + g;
                    const unsigned bh0 = *(const unsigned*)&Bh[rn * BG_STRIDE + kk + 2*tig];
                    const unsigned bh1 = *(const unsigned*)&Bh[rn * BG_STRIDE + kk + 8 + 2*tig];
                    const unsigned bl0 = *(const unsigned*)&Bl[rn * BG_STRIDE + kk + 2*tig];
                    const unsigned bl1 = *(const unsigned*)&Bl[rn * BG_STRIDE + kk + 8 + 2*tig];
                    #pragma unroll
                    for (int mt = 0; mt < 2; mt++) {
                        mma_bf16(acc[mt][nt], ah[mt], bh0, bh1);
                        mma_bf16(acc[mt][nt], ah[mt], bl0, bl1);
                        mma_bf16(acc[mt][nt], al[mt], bh0, bh1);
                    }
                }
            }
        }

        // store prefetched tile into the other buffer (safe: it was last
        // computed in iteration kt-1 and synced at end of kt-1)
        if (kt + 1 < NT) {
            const int nxt = cur ^ 1;
            __nv_bfloat16* Ah = smb + nxt * 4 * BG_MAT;
            __nv_bfloat16* Al = Ah + BG_MAT;
            __nv_bfloat16* Bh = Ah + 2 * BG_MAT;
            __nv_bfloat16* Bl = Ah + 3 * BG_MAT;
            const float vf[16] = { pv[0].x,pv[0].y,pv[0].z,pv[0].w,
                                   pv[1].x,pv[1].y,pv[1].z,pv[1].w,
                                   pv[2].x,pv[2].y,pv[2].z,pv[2].w,
                                   pv[3].x,pv[3].y,pv[3].z,pv[3].w };
            #pragma unroll
            for (int p = 0; p < 8; p++) {
                __nv_bfloat16 h0, l0, h1, l1;
                bf16_split(vf[2*p],     h0, l0);
                bf16_split(vf[2*p + 1], h1, l1);
                __nv_bfloat162 th; th.x = h0; th.y = h1;
                __nv_bfloat162 tl; tl.x = l0; tl.y = l1;
                *(__nv_bfloat162*)&Ah[ar * BG_STRIDE + akq + 2*p] = th;
                *(__nv_bfloat162*)&Al[ar * BG_STRIDE + akq + 2*p] = tl;
            }
            *(uint4*)&Bh[ar * BG_STRIDE + akq]     = pbh[0];
            *(uint4*)&Bh[ar * BG_STRIDE + akq + 8] = pbh[1];
            *(uint4*)&Bl[ar * BG_STRIDE + akq]     = pbl[0];
            *(uint4*)&Bl[ar * BG_STRIDE + akq + 8] = pbl[1];
            __syncthreads();
            cur = nxt;
        }
    }

    // epilogue (identical mapping to R8)
    #pragma unroll
    for (int mt = 0; mt < 2; mt++) {
        const long row = bm + m0 + mt * 16 + g;
        #pragma unroll
        for (int nt = 0; nt < 8; nt++) {
            const int col = bn + n0 + nt * 8 + 2 * tig;
            float c0 = acc[mt][nt][0], c1 = acc[mt][nt][1];
            float c2 = acc[mt][nt][2], c3 = acc[mt][nt][3];
            if (BIAS) {
                const float b0 = bias1[col]     + bias2[col];
                const float b1 = bias1[col + 1] + bias2[col + 1];
                c0 += b0; c1 += b1; c2 += b0; c3 += b1;
            }
            *(float2*)&C[row * Nn + col]       = make_float2(c0, c1);
            *(float2*)&C[(row + 8) * Nn + col] = make_float2(c2, c3);
        }
    }
}

// ----------------------------------------------------------------------------
// GAT attention + aggregation (proven R3 version).
// ----------------------------------------------------------------------------
__global__ void gat_attn(const float* __restrict__ a_src, const float* __restrict__ a_dst,
                         const float* __restrict__ bias, const int* __restrict__ edge_index,
                         int out_sel, int relu_flag)
{
    extern __shared__ __align__(16) float smem[];
    float* sH   = smem;
    float* sAs  = sH  + 8 * GROW;
    float* sAd  = sAs + 128;
    float* sB   = sAd + 128;
    float* s_as = sB  + 128;
    float* s_ad = s_as + 272;
    float* s_m  = s_ad + 272;
    float* s_dn = s_m  + 272;
    float* s_ev = s_dn + 272;
    int*   s_src = (int*)(s_ev + 1296);
    int*   s_dst = s_src + NEDGES;
    int*   s_cs  = s_dst + NEDGES;
    int*   s_ce  = s_cs + NNODES + 1;

    const int tid = threadIdx.x;

    if (tid == 0) {
        int cnt[NNODES];
        for (int n = 0; n < NNODES; n++) cnt[n] = 0;
        for (int e = 0; e < NEDGES; e++) {
            int s = (e < 64) ? edge_index[e]      : (e - 64);
            int d = (e < 64) ? edge_index[64 + e] : (e - 64);
            s_src[e] = s; s_dst[e] = d; cnt[d]++;
        }
        int off = 0;
        for (int n = 0; n < NNODES; n++) { s_cs[n] = off; off += cnt[n]; cnt[n] = s_cs[n]; }
        s_cs[NNODES] = off;
        for (int e = 0; e < NEDGES; e++) s_ce[cnt[s_dst[e]]++] = e;
    }
    if (tid < 128) { sAs[tid] = a_src[tid]; sAd[tid] = a_dst[tid]; sB[tid] = bias[tid]; }

    const float* Hsrc = g_tmpH + (long)blockIdx.x * (8 * GROW);
    for (int i = tid; i < (8 * GROW) / 4; i += 256)
        *(float4*)&sH[i * 4] = *(const float4*)&Hsrc[i * 4];
    __syncthreads();

    for (int i = tid; i < 8 * 64; i += 256) {
        const int g = i >> 6, t = i & 63;
        if (t < 34) {
            const int n = t >> 1, hh = t & 1;
            const float* hp = &sH[g * GROW + n * 128 + hh * 64];
            float as = 0.f, ad = 0.f;
            #pragma unroll 8
            for (int d = 0; d < 64; d++) {
                as += hp[d] * sAs[hh * 64 + d];
                ad += hp[d] * sAd[hh * 64 + d];
            }
            s_as[g * 34 + t] = as; s_ad[g * 34 + t] = ad;
        }
    }
    __syncthreads();

    for (int i = tid; i < 8 * 256; i += 256) {
        const int g = i >> 8, t = i & 255;
        if (t < 162) {
            const int e = t >> 1, hh = t & 1;
            const float raw = s_as[g * 34 + s_src[e] * 2 + hh]
                            + s_ad[g * 34 + s_dst[e] * 2 + hh];
            s_ev[g * 162 + t] = raw > 0.f ? raw : 0.2f * raw;
        }
    }
    __syncthreads();

    for (int i = tid; i < 8 * 64; i += 256) {
        const int g = i >> 6, t = i & 63;
        if (t < 34) {
            const int n = t >> 1, hh = t & 1;
            float m = -1e30f;
            for (int p = s_cs[n]; p < s_cs[n + 1]; p++)
                m = fmaxf(m, s_ev[g * 162 + s_ce[p] * 2 + hh]);
            float den = 0.f;
            for (int p = s_cs[n]; p < s_cs[n + 1]; p++)
                den += __expf(s_ev[g * 162 + s_ce[p] * 2 + hh] - m);
            s_m[g * 34 + t] = m; s_dn[g * 34 + t] = den;
        }
    }
    __syncthreads();

    for (int i = tid; i < 8 * 256; i += 256) {
        const int g = i >> 8, t = i & 255;
        if (t < 162) {
            const int e = t >> 1, hh = t & 1;
            const int d = s_dst[e];
            s_ev[g * 162 + t] = __expf(s_ev[g * 162 + t] - s_m[g * 34 + d * 2 + hh])
                                / (s_dn[g * 34 + d * 2 + hh] + 1e-16f);
        }
    }
    __syncthreads();

    float* outb = bufsel_w(out_sel);
    for (int i = tid; i < 8 * NNODES * 32; i += 256) {
        const int g = i / (NNODES * 32);
        const int r = i - g * (NNODES * 32);
        const int n = r >> 5;
        const int q = (r & 31) << 2;
        const int hh = q >> 6;
        float4 acc = make_float4(0.f, 0.f, 0.f, 0.f);
        for (int p = s_cs[n]; p < s_cs[n + 1]; p++) {
            const int e = s_ce[p];
            const float al = s_ev[g * 162 + e * 2 + hh];
            const float4 hv = *(const float4*)&sH[g * GROW + s_src[e] * 128 + q];
            acc.x += al * hv.x; acc.y += al * hv.y;
            acc.z += al * hv.z; acc.w += al * hv.w;
        }
        const float4 b4 = *(const float4*)&sB[q];
        acc.x += b4.x; acc.y += b4.y; acc.z += b4.z; acc.w += b4.w;
        if (relu_flag) {
            acc.x = fmaxf(acc.x, 0.f); acc.y = fmaxf(acc.y, 0.f);
            acc.z = fmaxf(acc.z, 0.f); acc.w = fmaxf(acc.w, 0.f);
        }
        *(float4*)&outb[((long)blockIdx.x * 8 + g) * GROW + n * 128 + q] = acc;
    }
}

// ----------------------------------------------------------------------------
// LSTM recurrence (persistent, 128 CTAs) — proven R3 version.
// ----------------------------------------------------------------------------
__global__ void lstm_recur(const float* __restrict__ whh, int out_sel)
{
    extern __shared__ __align__(16) float smem[];
    float* sW = smem;
    float* sH = sW + 128 * 129;
    float* sC = sH + 8 * 128;

    float* hseq = (out_sel == 0) ? g_h1 : g_h2;
    const float* pre = g_pre;

    const int tid = threadIdx.x;
    const int b0 = blockIdx.x * 8;
    const int d0 = blockIdx.y * 32;
    const unsigned nblocks = gridDim.x * gridDim.y;

    for (int i = tid; i < 128 * 128; i += blockDim.x) {
        const int r = i >> 7, k = i & 127;
        const int j = ((r >> 5) << 7) + d0 + (r & 31);
        sW[r * 129 + k] = whh[j * 128 + k];
    }
    {
        const int row = tid >> 5, l = tid & 31;
        sC[row * 32 + l] = 0.f;
        g_hstate[(b0 + row) * 128 + d0 + l] = 0.f;
    }
    grid_barrier(nblocks);

    for (int t = 0; t < SEQ; t++) {
        for (int i = tid; i < 8 * 128; i += blockDim.x) {
            const int row = i >> 7, k = i & 127;
            sH[i] = __ldcg(&g_hstate[(b0 + row) * 128 + k]);
        }
        __syncthreads();

        {
            const int row = tid >> 5, l = tid & 31;
            const float* hp = &sH[row * 128];
            const float* w0 = &sW[(l)      * 129];
            const float* w1 = &sW[(32 + l) * 129];
            const float* w2 = &sW[(64 + l) * 129];
            const float* w3 = &sW[(96 + l) * 129];
            const long pbase = ((long)(b0 + row) * SEQ + t) * GATES;
            float a0 = pre[pbase +       d0 + l];
            float a1 = pre[pbase + 128 + d0 + l];
            float a2 = pre[pbase + 256 + d0 + l];
            float a3 = pre[pbase + 384 + d0 + l];
            #pragma unroll 4
            for (int k = 0; k < 128; k++) {
                const float hv = hp[k];
                a0 += hv * w0[k]; a1 += hv * w1[k];
                a2 += hv * w2[k]; a3 += hv * w3[k];
            }
            const float ig = 1.f / (1.f + expf(-a0));
            const float fg = 1.f / (1.f + expf(-a1));
            const float gg = tanhf(a2);
            const float og = 1.f / (1.f + expf(-a3));
            const float c = fg * sC[row * 32 + l] + ig * gg;
            sC[row * 32 + l] = c;
            const float h = og * tanhf(c);
            g_hstate[(b0 + row) * 128 + d0 + l] = h;
            hseq[((long)(b0 + row) * SEQ + t) * 128 + d0 + l] = h;
        }
        grid_barrier(nblocks);
    }
}

// ----------------------------------------------------------------------------
// Temporal attention + FC head. One CTA (128 threads) per batch row.
// ----------------------------------------------------------------------------
__global__ void attn_fc(const float* __restrict__ attn_w, const float* __restrict__ attn_b,
                        const float* __restrict__ fc_w,   const float* __restrict__ fc_b,
                        float* __restrict__ out)
{
    __shared__ float sw[128];
    __shared__ float sc[SEQ];
    __shared__ float sctx[128];

    const int b = blockIdx.x, tid = threadIdx.x;
    const float* h2 = g_h2 + (long)b * SEQ * 128;

    sw[tid] = attn_w[tid];
    __syncthreads();

    if (tid < SEQ) {
        const float* hp = h2 + tid * 128;
        float acc = attn_b[0];
        #pragma unroll 8
        for (int k = 0; k < 128; k++) acc += hp[k] * sw[k];
        sc[tid] = tanhf(acc);
    }
    __syncthreads();

    if (tid == 0) {
        float m = -1e30f;
        for (int t = 0; t < SEQ; t++) m = fmaxf(m, sc[t]);
        float s = 0.f;
        for (int t = 0; t < SEQ; t++) { sc[t] = __expf(sc[t] - m); s += sc[t]; }
        const float inv = 1.f / s;
        for (int t = 0; t < SEQ; t++) sc[t] *= inv;
    }
    __syncthreads();

    {
        float acc = 0.f;
        for (int t = 0; t < SEQ; t++) acc += sc[t] * h2[t * 128 + tid];
        sctx[tid] = acc;
    }
    __syncthreads();

    if (tid < 10) {
        float acc = fc_b[tid];
        #pragma unroll 8
        for (int k = 0; k < 128; k++) acc += sctx[k] * fc_w[tid * 128 + k];
        out[b * 10 + tid] = acc;
    }
}

// ----------------------------------------------------------------------------
// Launcher
// ----------------------------------------------------------------------------
extern "C" void kernel_launch(void* const* d_in, const int* in_sizes, int n_in,
                              void* d_out, int out_size)
{
    const float* x    = (const float*)d_in[0];
    const int*   eidx = (const int*)  d_in[1];
    const float* gw[4]  = { (const float*)d_in[2],  (const float*)d_in[6],
                            (const float*)d_in[10], (const float*)d_in[14] };
    const float* gas[4] = { (const float*)d_in[3],  (const float*)d_in[7],
                            (const float*)d_in[11], (const float*)d_in[15] };
    const float* gad[4] = { (const float*)d_in[4],  (const float*)d_in[8],
                            (const float*)d_in[12], (const float*)d_in[16] };
    const float* gb[4]  = { (const float*)d_in[5],  (const float*)d_in[9],
                            (const float*)d_in[13], (const float*)d_in[17] };
    const float* wih0 = (const float*)d_in[18];
    const float* whh0 = (const float*)d_in[19];
    const float* bih0 = (const float*)d_in[20];
    const float* bhh0 = (const float*)d_in[21];
    const float* wih1 = (const float*)d_in[22];
    const float* whh1 = (const float*)d_in[23];
    const float* bih1 = (const float*)d_in[24];
    const float* bhh1 = (const float*)d_in[25];
    const float* attn_w = (const float*)d_in[26];
    const float* attn_b = (const float*)d_in[27];
    const float* fc_w   = (const float*)d_in[28];
    const float* fc_b   = (const float*)d_in[29];
    float* out = (float*)d_out;

    const int smem_attn = ((8 * GROW + 3 * 128 + 4 * 272 + 1296) +
                           (NEDGES * 3 + NNODES + 1 + 4)) * 4;
    const int smem_rec  = (128 * 129 + 8 * 128 + 8 * 32) * 4;
    const int smem_bg   = 2 * 4 * BG_MAT * 2;   // 81920 B

    cudaFuncSetAttribute((const void*)gat_attn,
                         cudaFuncAttributeMaxDynamicSharedMemorySize, smem_attn);
    cudaFuncSetAttribute((const void*)lstm_recur,
                         cudaFuncAttributeMaxDynamicSharedMemorySize, smem_rec);
    cudaFuncSetAttribute((const void*)bgemm<false>,
                         cudaFuncAttributeMaxDynamicSharedMemorySize, smem_bg);
    cudaFuncSetAttribute((const void*)bgemm<true>,
                         cudaFuncAttributeMaxDynamicSharedMemorySize, smem_bg);

    const int attn_grid = NG / 8;        // 2048
    const int mm_grid   = MROWS / 128;   // 2176

    // weight prep (bf16 hi/lo)
    prep_tn  <<<(GATES * LSTM_IN + 255) / 256, 256>>>(wih0, 0, GATES * LSTM_IN);
    prep_tn  <<<(GATES * HDIM    + 255) / 256, 256>>>(wih1, 1, GATES * HDIM);
    prep_nn_t<<<(HDIM * HDIM     + 255) / 256, 256>>>(gw[1], 2, HDIM, HDIM);
    prep_nn_t<<<(HDIM * HDIM     + 255) / 256, 256>>>(gw[2], 3, HDIM, HDIM);
    prep_nn_t<<<(HDIM * HDIM     + 255) / 256, 256>>>(gw[3], 4, HDIM, HDIM);

    // ---- GAT layer 0: x @ W0 -> tmpH -> attn -> bufA (relu)
    gat_mm0<<<(MROWS * 32) / 256, 256>>>(x, gw[0]);
    gat_attn<<<attn_grid, 256, smem_attn>>>(gas[0], gad[0], gb[0], eidx, 0, 1);

    // ---- GAT layer 1: bufA @ W1 -> tmpH -> attn -> bufB
    bgemm<false><<<dim3(mm_grid, 1), 256, smem_bg>>>(0, 2, nullptr, nullptr, 2, MROWS, 128, 128);
    gat_attn<<<attn_grid, 256, smem_attn>>>(gas[1], gad[1], gb[1], eidx, 1, 0);

    // ---- GAT layer 2: bufB @ W2 -> tmpH -> attn -> bufA (relu)
    bgemm<false><<<dim3(mm_grid, 1), 256, smem_bg>>>(1, 3, nullptr, nullptr, 2, MROWS, 128, 128);
    gat_attn<<<attn_grid, 256, smem_attn>>>(gas[2], gad[2], gb[2], eidx, 0, 1);

    // ---- GAT layer 3: bufA @ W3 -> tmpH -> attn -> bufB
    bgemm<false><<<dim3(mm_grid, 1), 256, smem_bg>>>(0, 4, nullptr, nullptr, 2, MROWS, 128, 128);
    gat_attn<<<attn_grid, 256, smem_attn>>>(gas[3], gad[3], gb[3], eidx, 1, 0);

    // ---- LSTM layer 0: pre-gates GEMM (A = bufB viewed [16384, 2176]) + recurrence
    bgemm<true><<<dim3(NG / 128, GATES / 128), 256, smem_bg>>>(1, 0, bih0, bhh0, 4, NG, GATES, LSTM_IN);
    lstm_recur<<<dim3(32, 4), 256, smem_rec>>>(whh0, 0);

    // ---- LSTM layer 1: pre-gates GEMM (A = g_h1 [16384,128]) + recurrence
    bgemm<true><<<dim3(NG / 128, GATES / 128), 256, smem_bg>>>(3, 1, bih1, bhh1, 4, NG, GATES, HDIM);
    lstm_recur<<<dim3(32, 4), 256, smem_rec>>>(whh1, 1);

    // ---- head
    attn_fc<<<BATCH, 128>>>(attn_w, attn_b, fc_w, fc_b, out);
}